// round 3
// baseline (speedup 1.0000x reference)
#include <cuda_runtime.h>
#include <math.h>

#define D_MODEL 1024
#define N_HEADS 16
#define HEAD_DIM 64
#define BATCH 2
#define SEQ 2048
#define M_TOT (BATCH * SEQ)   // 4096

// ---------------- scratch (no allocations allowed) ----------------
__device__ float g_q[BATCH * N_HEADS * SEQ * HEAD_DIM];   // [B,H,S,d]
__device__ float g_k[BATCH * N_HEADS * SEQ * HEAD_DIM];
__device__ float g_v[BATCH * N_HEADS * SEQ * HEAD_DIM];
__device__ float g_att[M_TOT * D_MODEL];                  // [B,S,C]

// =================================================================
// NT GEMM: C[M,N] = A[M,K] * W[N,K]^T, fp32, K = N = 1024, M = 4096
// MODE 0: C row-major [m*1024+n]
// MODE 1: write to head-major layout [b,h,s,d] (for Q/K/V)
// =================================================================
template <int MODE>
__global__ __launch_bounds__(256, 2)
void gemm_nt(const float* __restrict__ A, const float* __restrict__ W,
             float* __restrict__ C) {
    constexpr int BM = 128, BN = 128, BK = 16;
    __shared__ float As[BK][BM + 4];   // stride 132 floats (16B aligned)
    __shared__ float Bs[BK][BN + 4];

    const int bm = blockIdx.y * BM;
    const int bn = blockIdx.x * BN;
    const int tid = threadIdx.x;
    const int row = (tid / 16) * 8;    // 0..120
    const int col = (tid % 16) * 8;    // 0..120

    const float* Ab = A + (size_t)bm * 1024;
    const float* Wb = W + (size_t)bn * 1024;

    float acc[8][8];
#pragma unroll
    for (int i = 0; i < 8; i++)
#pragma unroll
        for (int j = 0; j < 8; j++) acc[i][j] = 0.f;

    for (int k0 = 0; k0 < 1024; k0 += BK) {
        // load 128x16 A and W tiles, transposed into smem
#pragma unroll
        for (int it = 0; it < 2; it++) {
            int f = tid + it * 256;        // 0..511
            int r = f >> 2;                // 0..127
            int kc = (f & 3) * 4;          // 0,4,8,12
            float4 va = *(const float4*)(Ab + (size_t)r * 1024 + k0 + kc);
            As[kc + 0][r] = va.x; As[kc + 1][r] = va.y;
            As[kc + 2][r] = va.z; As[kc + 3][r] = va.w;
            float4 vw = *(const float4*)(Wb + (size_t)r * 1024 + k0 + kc);
            Bs[kc + 0][r] = vw.x; Bs[kc + 1][r] = vw.y;
            Bs[kc + 2][r] = vw.z; Bs[kc + 3][r] = vw.w;
        }
        __syncthreads();

#pragma unroll
        for (int k = 0; k < BK; k++) {
            float a[8], b[8];
            *(float4*)(a)     = *(const float4*)&As[k][row];
            *(float4*)(a + 4) = *(const float4*)&As[k][row + 4];
            *(float4*)(b)     = *(const float4*)&Bs[k][col];
            *(float4*)(b + 4) = *(const float4*)&Bs[k][col + 4];
#pragma unroll
            for (int i = 0; i < 8; i++)
#pragma unroll
                for (int j = 0; j < 8; j++)
                    acc[i][j] = fmaf(a[i], b[j], acc[i][j]);
        }
        __syncthreads();
    }

    // store
#pragma unroll
    for (int i = 0; i < 8; i++) {
        int m = bm + row + i;
        if (MODE == 0) {
            float4* p = (float4*)(C + (size_t)m * 1024 + bn + col);
            p[0] = make_float4(acc[i][0], acc[i][1], acc[i][2], acc[i][3]);
            p[1] = make_float4(acc[i][4], acc[i][5], acc[i][6], acc[i][7]);
        } else {
            int n = bn + col;
            int h = n >> 6, d = n & 63;
            int b = m >> 11, s = m & 2047;
            float* o = C + (((size_t)(b * N_HEADS + h) * SEQ + s) * HEAD_DIM + d);
            ((float4*)o)[0] = make_float4(acc[i][0], acc[i][1], acc[i][2], acc[i][3]);
            ((float4*)o)[1] = make_float4(acc[i][4], acc[i][5], acc[i][6], acc[i][7]);
        }
    }
}

// =================================================================
// Flash attention, fp32, causal. 64x64 tiles, d=64. 256 threads,
// 4x4 per thread. Online softmax. Output -> [B,S,C] layout.
// =================================================================
#define AP 68   // padded row stride (keeps float4 alignment)

struct AttnSmem {
    float Qs[64][AP];
    float Ks[64][AP];
    float Vs[64][AP];
    float Ps[64][AP];
    float red_max[64][16];
    float red_sum[64][16];
    float mst[64];
    float lst[64];
};
#define ATTN_SMEM ((int)sizeof(AttnSmem))

extern __shared__ char attn_smem_raw[];

__global__ __launch_bounds__(256, 2)
void attn_kernel(const float* __restrict__ q, const float* __restrict__ k,
                 const float* __restrict__ v, float* __restrict__ out) {
    AttnSmem& S = *reinterpret_cast<AttnSmem*>(attn_smem_raw);
    const int qt = blockIdx.x;         // query tile (0..31)
    const int bh = blockIdx.y;         // b*H + h    (0..31)
    const int b = bh / N_HEADS, h = bh % N_HEADS;
    const size_t head_off = (size_t)bh * SEQ * HEAD_DIM;
    const float* Q = q + head_off;
    const float* K = k + head_off;
    const float* V = v + head_off;

    const int tid = threadIdx.x;
    const int ty = tid / 16, tx = tid % 16;
    const int r0 = ty * 4, c0 = tx * 4;
    const int q0 = qt * 64;

    // load Q tile (64x64)
#pragma unroll
    for (int it = 0; it < 4; it++) {
        int f = tid + it * 256;        // 0..1023 float4s
        int r = f >> 4;
        int c4 = (f & 15) * 4;
        float4 vq = *(const float4*)(Q + (size_t)(q0 + r) * HEAD_DIM + c4);
        *(float4*)&S.Qs[r][c4] = vq;
    }
    if (tid < 64) { S.mst[tid] = -1e30f; S.lst[tid] = 0.f; }

    float o[4][4];
#pragma unroll
    for (int i = 0; i < 4; i++)
#pragma unroll
        for (int j = 0; j < 4; j++) o[i][j] = 0.f;

    for (int jt = 0; jt <= qt; jt++) {
        const int k0b = jt * 64;
        // load K and V tiles
#pragma unroll
        for (int it = 0; it < 4; it++) {
            int f = tid + it * 256;
            int r = f >> 4;
            int c4 = (f & 15) * 4;
            *(float4*)&S.Ks[r][c4] =
                *(const float4*)(K + (size_t)(k0b + r) * HEAD_DIM + c4);
            *(float4*)&S.Vs[r][c4] =
                *(const float4*)(V + (size_t)(k0b + r) * HEAD_DIM + c4);
        }
        __syncthreads();   // (1) tiles ready; prev iter fully consumed

        // scores: sv[i][j] = (1/8) * Q[r0+i] . K[c0+j]
        float sv[4][4];
#pragma unroll
        for (int i = 0; i < 4; i++)
#pragma unroll
            for (int j = 0; j < 4; j++) sv[i][j] = 0.f;

        for (int kk = 0; kk < 64; kk += 4) {
            float4 qv[4], kv[4];
#pragma unroll
            for (int i = 0; i < 4; i++) qv[i] = *(const float4*)&S.Qs[r0 + i][kk];
#pragma unroll
            for (int j = 0; j < 4; j++) kv[j] = *(const float4*)&S.Ks[c0 + j][kk];
#pragma unroll
            for (int i = 0; i < 4; i++)
#pragma unroll
                for (int j = 0; j < 4; j++) {
                    sv[i][j] = fmaf(qv[i].x, kv[j].x, sv[i][j]);
                    sv[i][j] = fmaf(qv[i].y, kv[j].y, sv[i][j]);
                    sv[i][j] = fmaf(qv[i].z, kv[j].z, sv[i][j]);
                    sv[i][j] = fmaf(qv[i].w, kv[j].w, sv[i][j]);
                }
        }
        const float scale = 0.125f;   // 1/sqrt(64)
#pragma unroll
        for (int i = 0; i < 4; i++)
#pragma unroll
            for (int j = 0; j < 4; j++) sv[i][j] *= scale;

        if (jt == qt) {   // causal mask on diagonal tile
#pragma unroll
            for (int i = 0; i < 4; i++)
#pragma unroll
                for (int j = 0; j < 4; j++)
                    if (c0 + j > r0 + i) sv[i][j] = -10000.0f;
        }

        // local row max -> red_max
#pragma unroll
        for (int i = 0; i < 4; i++) {
            float m = sv[i][0];
            m = fmaxf(m, sv[i][1]); m = fmaxf(m, sv[i][2]); m = fmaxf(m, sv[i][3]);
            S.red_max[r0 + i][tx] = m;
        }
        __syncthreads();   // (2)

        float m_new[4], scale_o[4], lsum[4];
#pragma unroll
        for (int i = 0; i < 4; i++) {
            float m = S.mst[r0 + i];      // m_old
            float mt = -1e30f;
#pragma unroll
            for (int x = 0; x < 16; x++) mt = fmaxf(mt, S.red_max[r0 + i][x]);
            float mn = fmaxf(m, mt);
            m_new[i] = mn;
            scale_o[i] = __expf(m - mn);
            float ls = 0.f;
#pragma unroll
            for (int j = 0; j < 4; j++) {
                float p = __expf(sv[i][j] - mn);
                S.Ps[r0 + i][c0 + j] = p;
                ls += p;
            }
            lsum[i] = ls;
            S.red_sum[r0 + i][tx] = ls;
#pragma unroll
            for (int j = 0; j < 4; j++) o[i][j] *= scale_o[i];
        }
        __syncthreads();   // (3) Ps + red_sum visible

        // state update (one thread per row group)
        if (tx == 0) {
#pragma unroll
            for (int i = 0; i < 4; i++) {
                float lt = 0.f;
#pragma unroll
                for (int x = 0; x < 16; x++) lt += S.red_sum[r0 + i][x];
                S.mst[r0 + i] = m_new[i];
                S.lst[r0 + i] = S.lst[r0 + i] * scale_o[i] + lt;
            }
        }

        // O += P * V
        for (int kk = 0; kk < 64; kk += 4) {
            float4 pv[4];
#pragma unroll
            for (int i = 0; i < 4; i++) pv[i] = *(const float4*)&S.Ps[r0 + i][kk];
#pragma unroll
            for (int t = 0; t < 4; t++) {
                float4 vv = *(const float4*)&S.Vs[kk + t][c0];
                float pc[4] = {pv[0].x, pv[1].x, pv[2].x, pv[3].x};
                if (t == 1) { pc[0] = pv[0].y; pc[1] = pv[1].y; pc[2] = pv[2].y; pc[3] = pv[3].y; }
                if (t == 2) { pc[0] = pv[0].z; pc[1] = pv[1].z; pc[2] = pv[2].z; pc[3] = pv[3].z; }
                if (t == 3) { pc[0] = pv[0].w; pc[1] = pv[1].w; pc[2] = pv[2].w; pc[3] = pv[3].w; }
#pragma unroll
                for (int i = 0; i < 4; i++) {
                    o[i][0] = fmaf(pc[i], vv.x, o[i][0]);
                    o[i][1] = fmaf(pc[i], vv.y, o[i][1]);
                    o[i][2] = fmaf(pc[i], vv.z, o[i][2]);
                    o[i][3] = fmaf(pc[i], vv.w, o[i][3]);
                }
            }
        }
        __syncthreads();   // (4) done with Ps/Vs/red; state updated
    }

    // normalize + store to [B,S,C]
#pragma unroll
    for (int i = 0; i < 4; i++) {
        float inv_l = 1.0f / S.lst[r0 + i];
        int s = q0 + r0 + i;
        float* op = out + ((size_t)(b * SEQ + s) * D_MODEL + h * HEAD_DIM + c0);
        *(float4*)op = make_float4(o[i][0] * inv_l, o[i][1] * inv_l,
                                   o[i][2] * inv_l, o[i][3] * inv_l);
    }
}

// =================================================================
// launch
// =================================================================
extern "C" void kernel_launch(void* const* d_in, const int* in_sizes, int n_in,
                              void* d_out, int out_size) {
    const float* x  = (const float*)d_in[0];
    const float* wq = (const float*)d_in[1];
    const float* wk = (const float*)d_in[2];
    const float* wv = (const float*)d_in[3];
    const float* wo = (const float*)d_in[4];
    float* out = (float*)d_out;

    float *qb, *kb, *vb, *ab;
    cudaGetSymbolAddress((void**)&qb, g_q);
    cudaGetSymbolAddress((void**)&kb, g_k);
    cudaGetSymbolAddress((void**)&vb, g_v);
    cudaGetSymbolAddress((void**)&ab, g_att);

    cudaFuncSetAttribute(attn_kernel,
                         cudaFuncAttributeMaxDynamicSharedMemorySize, ATTN_SMEM);

    dim3 gemm_grid(D_MODEL / 128, M_TOT / 128);   // (8, 32)
    dim3 gemm_block(256);

    gemm_nt<1><<<gemm_grid, gemm_block>>>(x, wq, qb);
    gemm_nt<1><<<gemm_grid, gemm_block>>>(x, wk, kb);
    gemm_nt<1><<<gemm_grid, gemm_block>>>(x, wv, vb);

    dim3 attn_grid(SEQ / 64, BATCH * N_HEADS);    // (32, 32)
    attn_kernel<<<attn_grid, 256, ATTN_SMEM>>>(qb, kb, vb, ab);

    gemm_nt<0><<<gemm_grid, gemm_block>>>(ab, wo, out);
}

// round 6
// speedup vs baseline: 1.2170x; 1.2170x over previous
#include <cuda_runtime.h>
#include <cuda_bf16.h>
#include <cstdint>
#include <math.h>

#define D_MODEL 1024
#define N_HEADS 16
#define HEAD_DIM 64
#define BATCH 2
#define SEQ 2048
#define M_TOT (BATCH * SEQ)   // 4096

// ---------------- scratch (no allocations allowed) ----------------
__device__ float g_q[BATCH * N_HEADS * SEQ * HEAD_DIM];   // [B,H,S,d]
__device__ float g_k[BATCH * N_HEADS * SEQ * HEAD_DIM];
__device__ float g_v[BATCH * N_HEADS * SEQ * HEAD_DIM];
__device__ float g_att[M_TOT * D_MODEL];                  // [B,S,C]
__device__ __nv_bfloat16 g_x_hi[M_TOT * D_MODEL];
__device__ __nv_bfloat16 g_x_lo[M_TOT * D_MODEL];
__device__ __nv_bfloat16 g_w_hi[4 * D_MODEL * D_MODEL];   // wq,wk,wv,wo
__device__ __nv_bfloat16 g_w_lo[4 * D_MODEL * D_MODEL];
__device__ __nv_bfloat16 g_a_hi[M_TOT * D_MODEL];
__device__ __nv_bfloat16 g_a_lo[M_TOT * D_MODEL];

// =================== portable PTX helpers ===================
__device__ __forceinline__ uint32_t smem_u32(const void* p) {
    uint32_t a;
    asm("{ .reg .u64 t; cvta.to.shared.u64 t, %1; cvt.u32.u64 %0, t; }"
        : "=r"(a) : "l"(p));
    return a;
}

__device__ __forceinline__ void ldsm_x4(uint32_t* r, uint32_t addr) {
    asm volatile("ldmatrix.sync.aligned.m8n8.x4.shared.b16 {%0,%1,%2,%3}, [%4];"
                 : "=r"(r[0]), "=r"(r[1]), "=r"(r[2]), "=r"(r[3]) : "r"(addr));
}

// D += A * B  (m16n8k16, bf16 in, fp32 acc)
__device__ __forceinline__ void mma_bf16(float* d, const uint32_t* a,
                                         uint32_t b0, uint32_t b1) {
    asm volatile(
        "mma.sync.aligned.m16n8k16.row.col.f32.bf16.bf16.f32 "
        "{%0,%1,%2,%3}, {%4,%5,%6,%7}, {%8,%9}, {%0,%1,%2,%3};"
        : "+f"(d[0]), "+f"(d[1]), "+f"(d[2]), "+f"(d[3])
        : "r"(a[0]), "r"(a[1]), "r"(a[2]), "r"(a[3]), "r"(b0), "r"(b1));
}

// =================================================================
// split fp32 -> bf16 hi/lo pair
// =================================================================
__global__ __launch_bounds__(256)
void split_bf16(const float* __restrict__ in, __nv_bfloat16* __restrict__ hi,
                __nv_bfloat16* __restrict__ lo, int n4) {
    int i = blockIdx.x * 256 + threadIdx.x;
    if (i >= n4) return;
    float4 v = ((const float4*)in)[i];
    __nv_bfloat16 h0 = __float2bfloat16(v.x), h1 = __float2bfloat16(v.y);
    __nv_bfloat16 h2 = __float2bfloat16(v.z), h3 = __float2bfloat16(v.w);
    __nv_bfloat16 l0 = __float2bfloat16(v.x - __bfloat162float(h0));
    __nv_bfloat16 l1 = __float2bfloat16(v.y - __bfloat162float(h1));
    __nv_bfloat16 l2 = __float2bfloat16(v.z - __bfloat162float(h2));
    __nv_bfloat16 l3 = __float2bfloat16(v.w - __bfloat162float(h3));
    uint2 ph, pl;
    ph.x = (uint32_t)__bfloat16_as_ushort(h0) | ((uint32_t)__bfloat16_as_ushort(h1) << 16);
    ph.y = (uint32_t)__bfloat16_as_ushort(h2) | ((uint32_t)__bfloat16_as_ushort(h3) << 16);
    pl.x = (uint32_t)__bfloat16_as_ushort(l0) | ((uint32_t)__bfloat16_as_ushort(l1) << 16);
    pl.y = (uint32_t)__bfloat16_as_ushort(l2) | ((uint32_t)__bfloat16_as_ushort(l3) << 16);
    ((uint2*)hi)[i] = ph;
    ((uint2*)lo)[i] = pl;
}

// =================================================================
// mma.sync NT GEMM, bf16x3 compensated: C = A @ W^T, fp32-accurate.
// A[M,1024], W[N,1024] as (hi, lo) bf16 pairs.
// CTA tile 128x128, BK=32. 8 warps as 2(m) x 4(n); warp tile 64x32.
// MODE 0: C row-major.  MODE 1: C -> [b,h,s,d] head layout.
// =================================================================
#define SROW 40   // smem row stride in halves (32 data + 8 pad) = 80B

__global__ __launch_bounds__(256, 1)
void mma_gemm(const __nv_bfloat16* __restrict__ Ahi, const __nv_bfloat16* __restrict__ Alo,
              const __nv_bfloat16* __restrict__ Whi, const __nv_bfloat16* __restrict__ Wlo,
              float* __restrict__ C, int MODE) {
    __shared__ __nv_bfloat16 sAh[128 * SROW];
    __shared__ __nv_bfloat16 sAl[128 * SROW];
    __shared__ __nv_bfloat16 sBh[128 * SROW];
    __shared__ __nv_bfloat16 sBl[128 * SROW];

    const int tid = threadIdx.x;
    const int wid = tid >> 5, lane = tid & 31;
    const int wm = wid >> 2;            // 0..1  (64 rows each)
    const int wn = wid & 3;             // 0..3  (32 cols each)
    const int bm = blockIdx.y * 128;
    const int bn = blockIdx.x * 128;

    float acc[4][4][4];                 // [mtile][ntile][frag]
#pragma unroll
    for (int i = 0; i < 4; i++)
#pragma unroll
        for (int j = 0; j < 4; j++)
#pragma unroll
            for (int r = 0; r < 4; r++) acc[i][j][r] = 0.f;

    // ldmatrix base addresses (lane-dependent part precomputed)
    const int lrow = lane & 15;         // row within 16-row group
    const int lcol = (lane >> 4) * 8;   // 0 or 8 halves

    for (int ch = 0; ch < 32; ch++) {
        const int k0 = ch * 32;
        // ---- fill smem: 4 streams, 2 uint4 per thread per stream ----
#pragma unroll
        for (int i = 0; i < 2; i++) {
            int c = tid + i * 256;      // 0..511
            int row = c >> 2;           // 0..127
            int kc = (c & 3) * 8;       // halves: 0,8,16,24
            int so = row * SROW + kc;
            size_t ga = (size_t)(bm + row) * 1024 + k0 + kc;
            size_t gb = (size_t)(bn + row) * 1024 + k0 + kc;
            *(uint4*)&sAh[so] = *(const uint4*)(Ahi + ga);
            *(uint4*)&sAl[so] = *(const uint4*)(Alo + ga);
            *(uint4*)&sBh[so] = *(const uint4*)(Whi + gb);
            *(uint4*)&sBl[so] = *(const uint4*)(Wlo + gb);
        }
        __syncthreads();

#pragma unroll
        for (int ks = 0; ks < 32; ks += 16) {
            // A fragments: 4 m16 tiles, hi + lo
            uint32_t ah[4][4], al[4][4];
#pragma unroll
            for (int mi = 0; mi < 4; mi++) {
                int off = (wm * 64 + mi * 16 + lrow) * SROW + ks + lcol;
                ldsm_x4(ah[mi], smem_u32(&sAh[off]));
                ldsm_x4(al[mi], smem_u32(&sAl[off]));
            }
            // B fragments: 2 pairs of n8 tiles (x4 covers two tiles), hi + lo
            uint32_t bh[2][4], bl[2][4];
#pragma unroll
            for (int p = 0; p < 2; p++) {
                int off = (wn * 32 + p * 16 + lrow) * SROW + ks + lcol;
                ldsm_x4(bh[p], smem_u32(&sBh[off]));
                ldsm_x4(bl[p], smem_u32(&sBl[off]));
            }
            // MMAs: hi*hi + hi*lo + lo*hi
#pragma unroll
            for (int mi = 0; mi < 4; mi++)
#pragma unroll
                for (int ni = 0; ni < 4; ni++) {
                    int p = ni >> 1, q = ni & 1;
                    mma_bf16(acc[mi][ni], ah[mi], bh[p][q], bh[p][q + 2]);
                    mma_bf16(acc[mi][ni], ah[mi], bl[p][q], bl[p][q + 2]);
                    mma_bf16(acc[mi][ni], al[mi], bh[p][q], bh[p][q + 2]);
                }
        }
        __syncthreads();
    }

    // ---- epilogue ----
    const int r_in = lane >> 2;         // 0..7
    const int c_in = (lane & 3) * 2;    // 0,2,4,6
#pragma unroll
    for (int mi = 0; mi < 4; mi++) {
#pragma unroll
        for (int ni = 0; ni < 4; ni++) {
            int m0 = bm + wm * 64 + mi * 16 + r_in;
            int n  = bn + wn * 32 + ni * 8 + c_in;
            if (MODE == 0) {
                *(float2*)(C + (size_t)m0 * 1024 + n) =
                    make_float2(acc[mi][ni][0], acc[mi][ni][1]);
                *(float2*)(C + (size_t)(m0 + 8) * 1024 + n) =
                    make_float2(acc[mi][ni][2], acc[mi][ni][3]);
            } else {
                int h = n >> 6, d = n & 63;
#pragma unroll
                for (int rr = 0; rr < 2; rr++) {
                    int m = m0 + rr * 8;
                    int b = m >> 11, s = m & 2047;
                    float* o = C + (((size_t)(b * N_HEADS + h) * SEQ + s) * HEAD_DIM + d);
                    *(float2*)o = make_float2(acc[mi][ni][2 * rr], acc[mi][ni][2 * rr + 1]);
                }
            }
        }
    }
}

// =================================================================
// Flash attention, fp32, causal. 64x64 tiles, d=64. 256 threads,
// 4x4 per thread. Online softmax. Output -> [B,S,C] layout.
// (unchanged from the passing R2/R3 baseline)
// =================================================================
#define AP 68   // padded row stride (keeps float4 alignment)

struct AttnSmem {
    float Qs[64][AP];
    float Ks[64][AP];
    float Vs[64][AP];
    float Ps[64][AP];
    float red_max[64][16];
    float red_sum[64][16];
    float mst[64];
    float lst[64];
};
#define ATTN_SMEM ((int)sizeof(AttnSmem))

extern __shared__ char attn_smem_raw[];

__global__ __launch_bounds__(256, 2)
void attn_kernel(const float* __restrict__ q, const float* __restrict__ k,
                 const float* __restrict__ v, float* __restrict__ out) {
    AttnSmem& S = *reinterpret_cast<AttnSmem*>(attn_smem_raw);
    const int qt = blockIdx.x;
    const int bh = blockIdx.y;
    const int b = bh / N_HEADS, h = bh % N_HEADS;
    const size_t head_off = (size_t)bh * SEQ * HEAD_DIM;
    const float* Q = q + head_off;
    const float* K = k + head_off;
    const float* V = v + head_off;

    const int tid = threadIdx.x;
    const int ty = tid / 16, tx = tid % 16;
    const int r0 = ty * 4, c0 = tx * 4;
    const int q0 = qt * 64;

#pragma unroll
    for (int it = 0; it < 4; it++) {
        int f = tid + it * 256;
        int r = f >> 4;
        int c4 = (f & 15) * 4;
        float4 vq = *(const float4*)(Q + (size_t)(q0 + r) * HEAD_DIM + c4);
        *(float4*)&S.Qs[r][c4] = vq;
    }
    if (tid < 64) { S.mst[tid] = -1e30f; S.lst[tid] = 0.f; }

    float o[4][4];
#pragma unroll
    for (int i = 0; i < 4; i++)
#pragma unroll
        for (int j = 0; j < 4; j++) o[i][j] = 0.f;

    for (int jt = 0; jt <= qt; jt++) {
        const int k0b = jt * 64;
#pragma unroll
        for (int it = 0; it < 4; it++) {
            int f = tid + it * 256;
            int r = f >> 4;
            int c4 = (f & 15) * 4;
            *(float4*)&S.Ks[r][c4] =
                *(const float4*)(K + (size_t)(k0b + r) * HEAD_DIM + c4);
            *(float4*)&S.Vs[r][c4] =
                *(const float4*)(V + (size_t)(k0b + r) * HEAD_DIM + c4);
        }
        __syncthreads();

        float sv[4][4];
#pragma unroll
        for (int i = 0; i < 4; i++)
#pragma unroll
            for (int j = 0; j < 4; j++) sv[i][j] = 0.f;

        for (int kk = 0; kk < 64; kk += 4) {
            float4 qv[4], kv[4];
#pragma unroll
            for (int i = 0; i < 4; i++) qv[i] = *(const float4*)&S.Qs[r0 + i][kk];
#pragma unroll
            for (int j = 0; j < 4; j++) kv[j] = *(const float4*)&S.Ks[c0 + j][kk];
#pragma unroll
            for (int i = 0; i < 4; i++)
#pragma unroll
                for (int j = 0; j < 4; j++) {
                    sv[i][j] = fmaf(qv[i].x, kv[j].x, sv[i][j]);
                    sv[i][j] = fmaf(qv[i].y, kv[j].y, sv[i][j]);
                    sv[i][j] = fmaf(qv[i].z, kv[j].z, sv[i][j]);
                    sv[i][j] = fmaf(qv[i].w, kv[j].w, sv[i][j]);
                }
        }
        const float scale = 0.125f;
#pragma unroll
        for (int i = 0; i < 4; i++)
#pragma unroll
            for (int j = 0; j < 4; j++) sv[i][j] *= scale;

        if (jt == qt) {
#pragma unroll
            for (int i = 0; i < 4; i++)
#pragma unroll
                for (int j = 0; j < 4; j++)
                    if (c0 + j > r0 + i) sv[i][j] = -10000.0f;
        }

#pragma unroll
        for (int i = 0; i < 4; i++) {
            float m = sv[i][0];
            m = fmaxf(m, sv[i][1]); m = fmaxf(m, sv[i][2]); m = fmaxf(m, sv[i][3]);
            S.red_max[r0 + i][tx] = m;
        }
        __syncthreads();

        float m_new[4], scale_o[4], lsum[4];
#pragma unroll
        for (int i = 0; i < 4; i++) {
            float m = S.mst[r0 + i];
            float mt = -1e30f;
#pragma unroll
            for (int x = 0; x < 16; x++) mt = fmaxf(mt, S.red_max[r0 + i][x]);
            float mn = fmaxf(m, mt);
            m_new[i] = mn;
            scale_o[i] = __expf(m - mn);
            float ls = 0.f;
#pragma unroll
            for (int j = 0; j < 4; j++) {
                float p = __expf(sv[i][j] - mn);
                S.Ps[r0 + i][c0 + j] = p;
                ls += p;
            }
            lsum[i] = ls;
            S.red_sum[r0 + i][tx] = ls;
#pragma unroll
            for (int j = 0; j < 4; j++) o[i][j] *= scale_o[i];
        }
        __syncthreads();

        if (tx == 0) {
#pragma unroll
            for (int i = 0; i < 4; i++) {
                float lt = 0.f;
#pragma unroll
                for (int x = 0; x < 16; x++) lt += S.red_sum[r0 + i][x];
                S.mst[r0 + i] = m_new[i];
                S.lst[r0 + i] = S.lst[r0 + i] * scale_o[i] + lt;
            }
        }

        for (int kk = 0; kk < 64; kk += 4) {
            float4 pv[4];
#pragma unroll
            for (int i = 0; i < 4; i++) pv[i] = *(const float4*)&S.Ps[r0 + i][kk];
#pragma unroll
            for (int t = 0; t < 4; t++) {
                float4 vv = *(const float4*)&S.Vs[kk + t][c0];
                float pc[4] = {pv[0].x, pv[1].x, pv[2].x, pv[3].x};
                if (t == 1) { pc[0] = pv[0].y; pc[1] = pv[1].y; pc[2] = pv[2].y; pc[3] = pv[3].y; }
                if (t == 2) { pc[0] = pv[0].z; pc[1] = pv[1].z; pc[2] = pv[2].z; pc[3] = pv[3].z; }
                if (t == 3) { pc[0] = pv[0].w; pc[1] = pv[1].w; pc[2] = pv[2].w; pc[3] = pv[3].w; }
#pragma unroll
                for (int i = 0; i < 4; i++) {
                    o[i][0] = fmaf(pc[i], vv.x, o[i][0]);
                    o[i][1] = fmaf(pc[i], vv.y, o[i][1]);
                    o[i][2] = fmaf(pc[i], vv.z, o[i][2]);
                    o[i][3] = fmaf(pc[i], vv.w, o[i][3]);
                }
            }
        }
        __syncthreads();
    }

#pragma unroll
    for (int i = 0; i < 4; i++) {
        float inv_l = 1.0f / S.lst[r0 + i];
        int s = q0 + r0 + i;
        float* op = out + ((size_t)(b * SEQ + s) * D_MODEL + h * HEAD_DIM + c0);
        *(float4*)op = make_float4(o[i][0] * inv_l, o[i][1] * inv_l,
                                   o[i][2] * inv_l, o[i][3] * inv_l);
    }
}

// =================================================================
// launch
// =================================================================
extern "C" void kernel_launch(void* const* d_in, const int* in_sizes, int n_in,
                              void* d_out, int out_size) {
    const float* x  = (const float*)d_in[0];
    const float* wq = (const float*)d_in[1];
    const float* wk = (const float*)d_in[2];
    const float* wv = (const float*)d_in[3];
    const float* wo = (const float*)d_in[4];
    float* out = (float*)d_out;

    float *qb, *kb, *vb, *ab;
    __nv_bfloat16 *xh, *xl, *wh, *wl, *ah, *al;
    cudaGetSymbolAddress((void**)&qb, g_q);
    cudaGetSymbolAddress((void**)&kb, g_k);
    cudaGetSymbolAddress((void**)&vb, g_v);
    cudaGetSymbolAddress((void**)&ab, g_att);
    cudaGetSymbolAddress((void**)&xh, g_x_hi);
    cudaGetSymbolAddress((void**)&xl, g_x_lo);
    cudaGetSymbolAddress((void**)&wh, g_w_hi);
    cudaGetSymbolAddress((void**)&wl, g_w_lo);
    cudaGetSymbolAddress((void**)&ah, g_a_hi);
    cudaGetSymbolAddress((void**)&al, g_a_lo);

    cudaFuncSetAttribute(attn_kernel,
                         cudaFuncAttributeMaxDynamicSharedMemorySize, ATTN_SMEM);

    const int WN = D_MODEL * D_MODEL;   // 1M elems per weight

    // split inputs to bf16 hi/lo
    split_bf16<<<(M_TOT * D_MODEL / 4 + 255) / 256, 256>>>(x, xh, xl, M_TOT * D_MODEL / 4);
    split_bf16<<<(WN / 4 + 255) / 256, 256>>>(wq, wh + 0 * WN, wl + 0 * WN, WN / 4);
    split_bf16<<<(WN / 4 + 255) / 256, 256>>>(wk, wh + 1 * WN, wl + 1 * WN, WN / 4);
    split_bf16<<<(WN / 4 + 255) / 256, 256>>>(wv, wh + 2 * WN, wl + 2 * WN, WN / 4);
    split_bf16<<<(WN / 4 + 255) / 256, 256>>>(wo, wh + 3 * WN, wl + 3 * WN, WN / 4);

    dim3 gemm_grid(D_MODEL / 128, M_TOT / 128);   // (8, 32)
    mma_gemm<<<gemm_grid, 256>>>(xh, xl, wh + 0 * WN, wl + 0 * WN, qb, 1);
    mma_gemm<<<gemm_grid, 256>>>(xh, xl, wh + 1 * WN, wl + 1 * WN, kb, 1);
    mma_gemm<<<gemm_grid, 256>>>(xh, xl, wh + 2 * WN, wl + 2 * WN, vb, 1);

    dim3 attn_grid(SEQ / 64, BATCH * N_HEADS);    // (32, 32)
    attn_kernel<<<attn_grid, 256, ATTN_SMEM>>>(qb, kb, vb, ab);

    split_bf16<<<(M_TOT * D_MODEL / 4 + 255) / 256, 256>>>(ab, ah, al, M_TOT * D_MODEL / 4);
    mma_gemm<<<gemm_grid, 256>>>(ah, al, wh + 3 * WN, wl + 3 * WN, out, 0);
}

// round 7
// speedup vs baseline: 2.6419x; 2.1709x over previous
#include <cuda_runtime.h>
#include <cuda_bf16.h>
#include <cstdint>
#include <math.h>

#define D_MODEL 1024
#define N_HEADS 16
#define HEAD_DIM 64
#define BATCH 2
#define SEQ 2048
#define M_TOT (BATCH * SEQ)   // 4096

// ---------------- scratch (no allocations allowed) ----------------
__device__ __nv_bfloat16 g_x_hi[M_TOT * D_MODEL];
__device__ __nv_bfloat16 g_x_lo[M_TOT * D_MODEL];
__device__ __nv_bfloat16 g_w_hi[4 * D_MODEL * D_MODEL];   // wq,wk,wv,wo
__device__ __nv_bfloat16 g_w_lo[4 * D_MODEL * D_MODEL];
__device__ __nv_bfloat16 g_qh[M_TOT * D_MODEL], g_ql[M_TOT * D_MODEL];   // [b,h,s,d]
__device__ __nv_bfloat16 g_kh[M_TOT * D_MODEL], g_kl[M_TOT * D_MODEL];   // [b,h,s,d]
__device__ __nv_bfloat16 g_vth[M_TOT * D_MODEL], g_vtl[M_TOT * D_MODEL]; // [h*64+d][b*2048+s]
__device__ __nv_bfloat16 g_ah[M_TOT * D_MODEL], g_al[M_TOT * D_MODEL];   // [m][1024]

// =================== portable PTX helpers ===================
__device__ __forceinline__ uint32_t smem_u32(const void* p) {
    uint32_t a;
    asm("{ .reg .u64 t; cvta.to.shared.u64 t, %1; cvt.u32.u64 %0, t; }"
        : "=r"(a) : "l"(p));
    return a;
}

__device__ __forceinline__ void ldsm_x4(uint32_t* r, uint32_t addr) {
    asm volatile("ldmatrix.sync.aligned.m8n8.x4.shared.b16 {%0,%1,%2,%3}, [%4];"
                 : "=r"(r[0]), "=r"(r[1]), "=r"(r[2]), "=r"(r[3]) : "r"(addr));
}

// D += A * B  (m16n8k16, bf16 in, fp32 acc)
__device__ __forceinline__ void mma_bf16(float* d, const uint32_t* a,
                                         uint32_t b0, uint32_t b1) {
    asm volatile(
        "mma.sync.aligned.m16n8k16.row.col.f32.bf16.bf16.f32 "
        "{%0,%1,%2,%3}, {%4,%5,%6,%7}, {%8,%9}, {%0,%1,%2,%3};"
        : "+f"(d[0]), "+f"(d[1]), "+f"(d[2]), "+f"(d[3])
        : "r"(a[0]), "r"(a[1]), "r"(a[2]), "r"(a[3]), "r"(b0), "r"(b1));
}

__device__ __forceinline__ void cp16(void* dst_smem, const void* src) {
    uint32_t d = smem_u32(dst_smem);
    asm volatile("cp.async.cg.shared.global [%0], [%1], 16;" :: "r"(d), "l"(src) : "memory");
}
#define CP_COMMIT() asm volatile("cp.async.commit_group;" ::: "memory")

// split v -> bf16 hi + bf16 lo (packed pairs)
__device__ __forceinline__ void pack_hl(float v0, float v1, uint32_t& hi, uint32_t& lo) {
    __nv_bfloat162 h = __floats2bfloat162_rn(v0, v1);
    __nv_bfloat162 l = __floats2bfloat162_rn(v0 - __bfloat162float(h.x),
                                             v1 - __bfloat162float(h.y));
    hi = *(uint32_t*)&h;
    lo = *(uint32_t*)&l;
}
__device__ __forceinline__ void store_pair(__nv_bfloat16* Oh, __nv_bfloat16* Ol,
                                           size_t off, float v0, float v1) {
    __nv_bfloat162 h = __floats2bfloat162_rn(v0, v1);
    __nv_bfloat162 l = __floats2bfloat162_rn(v0 - __bfloat162float(h.x),
                                             v1 - __bfloat162float(h.y));
    *(__nv_bfloat162*)(Oh + off) = h;
    *(__nv_bfloat162*)(Ol + off) = l;
}

// =================================================================
// split fp32 -> bf16 hi/lo pair (x and weights only)
// =================================================================
__global__ __launch_bounds__(256)
void split_bf16(const float* __restrict__ in, __nv_bfloat16* __restrict__ hi,
                __nv_bfloat16* __restrict__ lo, int n4) {
    int i = blockIdx.x * 256 + threadIdx.x;
    if (i >= n4) return;
    float4 v = ((const float4*)in)[i];
    uint32_t h0, l0, h1, l1;
    pack_hl(v.x, v.y, h0, l0);
    pack_hl(v.z, v.w, h1, l1);
    ((uint2*)hi)[i] = make_uint2(h0, h1);
    ((uint2*)lo)[i] = make_uint2(l0, l1);
}

// =================================================================
// mma.sync NT GEMM, bf16x3 compensated, cp.async double-buffered.
// C[M,N] = A[M,1024] @ W[N,1024]^T. CTA tile 128x128, BK=32, 8 warps.
// MODE 0: fp32 row-major C (ldc)
// MODE 1: bf16 hi/lo -> [b,h,s,d] head layout (Q, K)
// MODE 3: bf16 hi/lo row-major (ldc)        (V-transposed via swapped ops)
// =================================================================
#define SROW 40                        // smem row stride in halves
#define STAGE_B (128 * SROW * 2)       // 10240 B per tile
#define GSTAGE (4 * STAGE_B)           // 40960 B per stage
#define GEMM_SMEM (2 * GSTAGE)         // 81920 B

__global__ __launch_bounds__(256, 1)
void mma_gemm(const __nv_bfloat16* __restrict__ Ahi, const __nv_bfloat16* __restrict__ Alo,
              const __nv_bfloat16* __restrict__ Whi, const __nv_bfloat16* __restrict__ Wlo,
              float* __restrict__ C, __nv_bfloat16* __restrict__ Oh,
              __nv_bfloat16* __restrict__ Ol, int ldc, int MODE) {
    extern __shared__ char gsm[];
    const int tid = threadIdx.x;
    const int wid = tid >> 5, lane = tid & 31;
    const int wm = wid >> 2, wn = wid & 3;
    const int bm = blockIdx.y * 128, bn = blockIdx.x * 128;

    float acc[4][4][4];
#pragma unroll
    for (int i = 0; i < 4; i++)
#pragma unroll
        for (int j = 0; j < 4; j++)
#pragma unroll
            for (int r = 0; r < 4; r++) acc[i][j][r] = 0.f;

    const int lrow = lane & 15, lcol = (lane >> 4) * 8;

    auto fill = [&](int st, int k0) {
        char* base = gsm + st * GSTAGE;
#pragma unroll
        for (int i = 0; i < 2; i++) {
            int c = tid + i * 256;
            int row = c >> 2, kc = (c & 3) * 8;
            int so = (row * SROW + kc) * 2;
            size_t ga = (size_t)(bm + row) * 1024 + k0 + kc;
            size_t gb = (size_t)(bn + row) * 1024 + k0 + kc;
            cp16(base + so, Ahi + ga);
            cp16(base + STAGE_B + so, Alo + ga);
            cp16(base + 2 * STAGE_B + so, Whi + gb);
            cp16(base + 3 * STAGE_B + so, Wlo + gb);
        }
        CP_COMMIT();
    };

    fill(0, 0);
    for (int ch = 0; ch < 32; ch++) {
        if (ch + 1 < 32) {
            fill((ch + 1) & 1, (ch + 1) * 32);
            asm volatile("cp.async.wait_group 1;" ::: "memory");
        } else {
            asm volatile("cp.async.wait_group 0;" ::: "memory");
        }
        __syncthreads();
        char* base = gsm + (ch & 1) * GSTAGE;
        __nv_bfloat16* sAh = (__nv_bfloat16*)base;
        __nv_bfloat16* sAl = (__nv_bfloat16*)(base + STAGE_B);
        __nv_bfloat16* sBh = (__nv_bfloat16*)(base + 2 * STAGE_B);
        __nv_bfloat16* sBl = (__nv_bfloat16*)(base + 3 * STAGE_B);

#pragma unroll
        for (int ks = 0; ks < 32; ks += 16) {
            uint32_t ah[4][4], al[4][4], bh[2][4], bl[2][4];
#pragma unroll
            for (int mi = 0; mi < 4; mi++) {
                int off = (wm * 64 + mi * 16 + lrow) * SROW + ks + lcol;
                ldsm_x4(ah[mi], smem_u32(sAh + off));
                ldsm_x4(al[mi], smem_u32(sAl + off));
            }
#pragma unroll
            for (int p = 0; p < 2; p++) {
                int off = (wn * 32 + p * 16 + lrow) * SROW + ks + lcol;
                ldsm_x4(bh[p], smem_u32(sBh + off));
                ldsm_x4(bl[p], smem_u32(sBl + off));
            }
#pragma unroll
            for (int mi = 0; mi < 4; mi++)
#pragma unroll
                for (int ni = 0; ni < 4; ni++) {
                    int p = ni >> 1, q = ni & 1;
                    mma_bf16(acc[mi][ni], ah[mi], bh[p][q], bh[p][q + 2]);
                    mma_bf16(acc[mi][ni], ah[mi], bl[p][q], bl[p][q + 2]);
                    mma_bf16(acc[mi][ni], al[mi], bh[p][q], bh[p][q + 2]);
                }
        }
        __syncthreads();
    }

    // ---- epilogue ----
    const int r_in = lane >> 2, c_in = (lane & 3) * 2;
#pragma unroll
    for (int mi = 0; mi < 4; mi++) {
#pragma unroll
        for (int ni = 0; ni < 4; ni++) {
            int m0 = bm + wm * 64 + mi * 16 + r_in;
            int n  = bn + wn * 32 + ni * 8 + c_in;
            float v0 = acc[mi][ni][0], v1 = acc[mi][ni][1];
            float v2 = acc[mi][ni][2], v3 = acc[mi][ni][3];
            if (MODE == 0) {
                *(float2*)(C + (size_t)m0 * ldc + n) = make_float2(v0, v1);
                *(float2*)(C + (size_t)(m0 + 8) * ldc + n) = make_float2(v2, v3);
            } else if (MODE == 3) {
                store_pair(Oh, Ol, (size_t)m0 * ldc + n, v0, v1);
                store_pair(Oh, Ol, (size_t)(m0 + 8) * ldc + n, v2, v3);
            } else {  // MODE 1: [b,h,s,d]
                int h = n >> 6, d = n & 63;
#pragma unroll
                for (int rr = 0; rr < 2; rr++) {
                    int m = m0 + rr * 8;
                    int b = m >> 11, s = m & 2047;
                    size_t off = ((size_t)((b * N_HEADS + h) * SEQ + s)) * HEAD_DIM + d;
                    store_pair(Oh, Ol, off, acc[mi][ni][2 * rr], acc[mi][ni][2 * rr + 1]);
                }
            }
        }
    }
}

// =================================================================
// Flash attention on mma.sync, bf16x3 compensated, causal.
// CTA: 128 q rows x full head. 8 warps, warp = 16 q rows. Key tiles 64.
// Q,K from [b,h,s,d] hi/lo; V transposed [h*64+d][b*2048+s] hi/lo.
// Output: bf16 hi/lo [m][1024] for the O-projection GEMM.
// =================================================================
#define ASROW 72

__global__ __launch_bounds__(256, 1)
void attn_kernel(const __nv_bfloat16* __restrict__ Qh, const __nv_bfloat16* __restrict__ Ql,
                 const __nv_bfloat16* __restrict__ Kh, const __nv_bfloat16* __restrict__ Kl,
                 const __nv_bfloat16* __restrict__ Vh, const __nv_bfloat16* __restrict__ Vl,
                 __nv_bfloat16* __restrict__ Ohg, __nv_bfloat16* __restrict__ Olg) {
    __shared__ __nv_bfloat16 sKh[64 * ASROW], sKl[64 * ASROW];
    __shared__ __nv_bfloat16 sVh[64 * ASROW], sVl[64 * ASROW];

    const int tid = threadIdx.x, wid = tid >> 5, lane = tid & 31;
    const int qt = blockIdx.x, bh = blockIdx.y;
    const int b = bh >> 4, h = bh & 15;
    const int q0 = qt * 128;
    const size_t qkbase = (size_t)bh * SEQ * HEAD_DIM;
    const size_t vbase = (size_t)(h * 64) * 4096 + (size_t)b * 2048;

    const int lrow = lane & 15, lcol = (lane >> 4) * 8;
    const int rA = lane >> 2;           // row within 8 (and +8 for B half)
    const int tig2 = (lane & 3) * 2;    // col pair base

    // ---- stage Q into fragments (two passes through K buffers) ----
    uint32_t qfh[4][4], qfl[4][4];
    for (int ph = 0; ph < 2; ph++) {
        const __nv_bfloat16* src = ph ? Ql : Qh;
#pragma unroll
        for (int i = 0; i < 4; i++) {
            int c = tid + i * 256;
            int row = c >> 3, cc = (c & 7) * 8;
            __nv_bfloat16* dst = (row < 64 ? sKh : sKl) + (row & 63) * ASROW + cc;
            *(uint4*)dst = *(const uint4*)(src + qkbase + (size_t)(q0 + row) * 64 + cc);
        }
        __syncthreads();
        int qr = wid * 16 + lrow;
        const __nv_bfloat16* buf = (qr < 64) ? sKh : sKl;
        int qrl = qr & 63;
#pragma unroll
        for (int ks = 0; ks < 4; ks++) {
            if (ph == 0) ldsm_x4(qfh[ks], smem_u32(buf + qrl * ASROW + ks * 16 + lcol));
            else         ldsm_x4(qfl[ks], smem_u32(buf + qrl * ASROW + ks * 16 + lcol));
        }
        __syncthreads();
    }

    float oacc[8][4];
#pragma unroll
    for (int i = 0; i < 8; i++)
#pragma unroll
        for (int j = 0; j < 4; j++) oacc[i][j] = 0.f;
    float mMA = -1e30f, mMB = -1e30f, lA = 0.f, lB = 0.f;

    const int nt = 2 * qt + 2;
    for (int jt = 0; jt < nt; jt++) {
        const int k0 = jt * 64;
        // ---- fill K hi/lo and Vt hi/lo tiles ----
#pragma unroll
        for (int i = 0; i < 2; i++) {
            int c = tid + i * 256;
            int row = c >> 3, cc = (c & 7) * 8;
            int so = row * ASROW + cc;
            *(uint4*)(sKh + so) = *(const uint4*)(Kh + qkbase + (size_t)(k0 + row) * 64 + cc);
            *(uint4*)(sKl + so) = *(const uint4*)(Kl + qkbase + (size_t)(k0 + row) * 64 + cc);
            *(uint4*)(sVh + so) = *(const uint4*)(Vh + vbase + (size_t)row * 4096 + k0 + cc);
            *(uint4*)(sVl + so) = *(const uint4*)(Vl + vbase + (size_t)row * 4096 + k0 + cc);
        }
        __syncthreads();

        const int wrow0 = q0 + wid * 16;
        if (k0 <= wrow0 + 15) {         // warp has at least one unmasked key
            // ---- scores S = Q K^T (3 compensated combos) ----
            float sacc[8][4];
#pragma unroll
            for (int i = 0; i < 8; i++)
#pragma unroll
                for (int j = 0; j < 4; j++) sacc[i][j] = 0.f;
#pragma unroll
            for (int ks = 0; ks < 4; ks++) {
                uint32_t kfh[4][4], kfl[4][4];
#pragma unroll
                for (int p = 0; p < 4; p++) {
                    int off = (p * 16 + lrow) * ASROW + ks * 16 + lcol;
                    ldsm_x4(kfh[p], smem_u32(sKh + off));
                    ldsm_x4(kfl[p], smem_u32(sKl + off));
                }
#pragma unroll
                for (int ni = 0; ni < 8; ni++) {
                    int p = ni >> 1, qq = ni & 1;
                    mma_bf16(sacc[ni], qfh[ks], kfh[p][qq], kfh[p][qq + 2]);
                    mma_bf16(sacc[ni], qfh[ks], kfl[p][qq], kfl[p][qq + 2]);
                    mma_bf16(sacc[ni], qfl[ks], kfh[p][qq], kfh[p][qq + 2]);
                }
            }
            // ---- scale + causal mask ----
            const bool band = (k0 + 63 > wrow0);
            const int rowAg = wrow0 + rA, rowBg = rowAg + 8;
#pragma unroll
            for (int ni = 0; ni < 8; ni++) {
                int colb = k0 + ni * 8 + tig2;
#pragma unroll
                for (int e = 0; e < 4; e++) {
                    float s = sacc[ni][e] * 0.125f;
                    if (band) {
                        int col = colb + (e & 1);
                        int row = (e < 2) ? rowAg : rowBg;
                        if (col > row) s = -1e30f;
                    }
                    sacc[ni][e] = s;
                }
            }
            // ---- online softmax ----
            float mxA = -1e30f, mxB = -1e30f;
#pragma unroll
            for (int ni = 0; ni < 8; ni++) {
                mxA = fmaxf(mxA, fmaxf(sacc[ni][0], sacc[ni][1]));
                mxB = fmaxf(mxB, fmaxf(sacc[ni][2], sacc[ni][3]));
            }
            mxA = fmaxf(mxA, __shfl_xor_sync(0xffffffffu, mxA, 1));
            mxA = fmaxf(mxA, __shfl_xor_sync(0xffffffffu, mxA, 2));
            mxB = fmaxf(mxB, __shfl_xor_sync(0xffffffffu, mxB, 1));
            mxB = fmaxf(mxB, __shfl_xor_sync(0xffffffffu, mxB, 2));
            float mnA = fmaxf(mMA, mxA), mnB = fmaxf(mMB, mxB);
            float scA = __expf(mMA - mnA), scB = __expf(mMB - mnB);
            mMA = mnA; mMB = mnB;
            float suA = 0.f, suB = 0.f;
#pragma unroll
            for (int ni = 0; ni < 8; ni++) {
                sacc[ni][0] = __expf(sacc[ni][0] - mnA); suA += sacc[ni][0];
                sacc[ni][1] = __expf(sacc[ni][1] - mnA); suA += sacc[ni][1];
                sacc[ni][2] = __expf(sacc[ni][2] - mnB); suB += sacc[ni][2];
                sacc[ni][3] = __expf(sacc[ni][3] - mnB); suB += sacc[ni][3];
            }
            suA += __shfl_xor_sync(0xffffffffu, suA, 1);
            suA += __shfl_xor_sync(0xffffffffu, suA, 2);
            suB += __shfl_xor_sync(0xffffffffu, suB, 1);
            suB += __shfl_xor_sync(0xffffffffu, suB, 2);
            lA = lA * scA + suA;
            lB = lB * scB + suB;
#pragma unroll
            for (int ni = 0; ni < 8; ni++) {
                oacc[ni][0] *= scA; oacc[ni][1] *= scA;
                oacc[ni][2] *= scB; oacc[ni][3] *= scB;
            }
            // ---- O += P * V^T  (P repacked C-frag -> A-frag, hi/lo) ----
#pragma unroll
            for (int j = 0; j < 4; j++) {
                uint32_t Ph[4], Pl[4];
                pack_hl(sacc[2 * j][0],     sacc[2 * j][1],     Ph[0], Pl[0]);
                pack_hl(sacc[2 * j][2],     sacc[2 * j][3],     Ph[1], Pl[1]);
                pack_hl(sacc[2 * j + 1][0], sacc[2 * j + 1][1], Ph[2], Pl[2]);
                pack_hl(sacc[2 * j + 1][2], sacc[2 * j + 1][3], Ph[3], Pl[3]);
                uint32_t vfh[4][4], vfl[4][4];
#pragma unroll
                for (int p = 0; p < 4; p++) {
                    int off = (p * 16 + lrow) * ASROW + j * 16 + lcol;
                    ldsm_x4(vfh[p], smem_u32(sVh + off));
                    ldsm_x4(vfl[p], smem_u32(sVl + off));
                }
#pragma unroll
                for (int ni = 0; ni < 8; ni++) {
                    int p = ni >> 1, qq = ni & 1;
                    mma_bf16(oacc[ni], Ph, vfh[p][qq], vfh[p][qq + 2]);
                    mma_bf16(oacc[ni], Ph, vfl[p][qq], vfl[p][qq + 2]);
                    mma_bf16(oacc[ni], Pl, vfh[p][qq], vfh[p][qq + 2]);
                }
            }
        }
        __syncthreads();
    }

    // ---- normalize + store bf16 hi/lo to [m][1024] ----
    float iA = 1.f / lA, iB = 1.f / lB;
    int sA = q0 + wid * 16 + rA;
    size_t rowA_off = ((size_t)b * SEQ + sA) * D_MODEL + h * 64;
    size_t rowB_off = rowA_off + (size_t)8 * D_MODEL;
#pragma unroll
    for (int ni = 0; ni < 8; ni++) {
        int n = ni * 8 + tig2;
        store_pair(Ohg, Olg, rowA_off + n, oacc[ni][0] * iA, oacc[ni][1] * iA);
        store_pair(Ohg, Olg, rowB_off + n, oacc[ni][2] * iB, oacc[ni][3] * iB);
    }
}

// =================================================================
// launch
// =================================================================
extern "C" void kernel_launch(void* const* d_in, const int* in_sizes, int n_in,
                              void* d_out, int out_size) {
    const float* x  = (const float*)d_in[0];
    const float* wq = (const float*)d_in[1];
    const float* wk = (const float*)d_in[2];
    const float* wv = (const float*)d_in[3];
    const float* wo = (const float*)d_in[4];
    float* out = (float*)d_out;

    __nv_bfloat16 *xh, *xl, *wh, *wl, *qh, *ql, *kh, *kl, *vth, *vtl, *ah, *al;
    cudaGetSymbolAddress((void**)&xh, g_x_hi);
    cudaGetSymbolAddress((void**)&xl, g_x_lo);
    cudaGetSymbolAddress((void**)&wh, g_w_hi);
    cudaGetSymbolAddress((void**)&wl, g_w_lo);
    cudaGetSymbolAddress((void**)&qh, g_qh);
    cudaGetSymbolAddress((void**)&ql, g_ql);
    cudaGetSymbolAddress((void**)&kh, g_kh);
    cudaGetSymbolAddress((void**)&kl, g_kl);
    cudaGetSymbolAddress((void**)&vth, g_vth);
    cudaGetSymbolAddress((void**)&vtl, g_vtl);
    cudaGetSymbolAddress((void**)&ah, g_ah);
    cudaGetSymbolAddress((void**)&al, g_al);

    cudaFuncSetAttribute(mma_gemm,
                         cudaFuncAttributeMaxDynamicSharedMemorySize, GEMM_SMEM);

    const int WN = D_MODEL * D_MODEL;   // 1M elems per weight

    // split x + weights to bf16 hi/lo
    split_bf16<<<(M_TOT * D_MODEL / 4 + 255) / 256, 256>>>(x, xh, xl, M_TOT * D_MODEL / 4);
    split_bf16<<<(WN / 4 + 255) / 256, 256>>>(wq, wh + 0 * WN, wl + 0 * WN, WN / 4);
    split_bf16<<<(WN / 4 + 255) / 256, 256>>>(wk, wh + 1 * WN, wl + 1 * WN, WN / 4);
    split_bf16<<<(WN / 4 + 255) / 256, 256>>>(wv, wh + 2 * WN, wl + 2 * WN, WN / 4);
    split_bf16<<<(WN / 4 + 255) / 256, 256>>>(wo, wh + 3 * WN, wl + 3 * WN, WN / 4);

    // Q, K projections -> bf16 hi/lo head layout
    dim3 g_qko(D_MODEL / 128, M_TOT / 128);   // (8, 32)
    mma_gemm<<<g_qko, 256, GEMM_SMEM>>>(xh, xl, wh + 0 * WN, wl + 0 * WN,
                                        nullptr, qh, ql, 0, 1);
    mma_gemm<<<g_qko, 256, GEMM_SMEM>>>(xh, xl, wh + 1 * WN, wl + 1 * WN,
                                        nullptr, kh, kl, 0, 1);
    // V projection TRANSPOSED: C' = wv @ x^T -> [channel][token], bf16 hi/lo
    dim3 g_v(M_TOT / 128, D_MODEL / 128);     // (32, 8)
    mma_gemm<<<g_v, 256, GEMM_SMEM>>>(wh + 2 * WN, wl + 2 * WN, xh, xl,
                                      nullptr, vth, vtl, M_TOT, 3);

    // attention -> bf16 hi/lo [m][1024]
    dim3 g_at(SEQ / 128, BATCH * N_HEADS);    // (16, 32)
    attn_kernel<<<g_at, 256>>>(qh, ql, kh, kl, vth, vtl, ah, al);

    // output projection -> fp32 out
    mma_gemm<<<g_qko, 256, GEMM_SMEM>>>(ah, al, wh + 3 * WN, wl + 3 * WN,
                                        out, nullptr, nullptr, D_MODEL, 0);
}

// round 8
// speedup vs baseline: 2.7550x; 1.0428x over previous
#include <cuda_runtime.h>
#include <cuda_bf16.h>
#include <cstdint>
#include <math.h>

#define D_MODEL 1024
#define N_HEADS 16
#define HEAD_DIM 64
#define BATCH 2
#define SEQ 2048
#define M_TOT (BATCH * SEQ)   // 4096
#define WN (D_MODEL * D_MODEL)

// ---------------- scratch (no allocations allowed) ----------------
__device__ __nv_bfloat16 g_x_hi[M_TOT * D_MODEL];
__device__ __nv_bfloat16 g_x_lo[M_TOT * D_MODEL];
__device__ __nv_bfloat16 g_w_hi[4 * WN];   // wq,wk,wv,wo
__device__ __nv_bfloat16 g_w_lo[4 * WN];
__device__ __nv_bfloat16 g_qh[M_TOT * D_MODEL], g_ql[M_TOT * D_MODEL];   // [b,h,s,d]
__device__ __nv_bfloat16 g_kh[M_TOT * D_MODEL], g_kl[M_TOT * D_MODEL];   // [b,h,s,d]
__device__ __nv_bfloat16 g_vth[M_TOT * D_MODEL], g_vtl[M_TOT * D_MODEL]; // [h*64+d][b*2048+s]
__device__ __nv_bfloat16 g_ah[M_TOT * D_MODEL], g_al[M_TOT * D_MODEL];   // [m][1024]

// =================== portable PTX helpers ===================
__device__ __forceinline__ uint32_t smem_u32(const void* p) {
    uint32_t a;
    asm("{ .reg .u64 t; cvta.to.shared.u64 t, %1; cvt.u32.u64 %0, t; }"
        : "=r"(a) : "l"(p));
    return a;
}

__device__ __forceinline__ void ldsm_x4(uint32_t* r, uint32_t addr) {
    asm volatile("ldmatrix.sync.aligned.m8n8.x4.shared.b16 {%0,%1,%2,%3}, [%4];"
                 : "=r"(r[0]), "=r"(r[1]), "=r"(r[2]), "=r"(r[3]) : "r"(addr));
}

// D += A * B  (m16n8k16, bf16 in, fp32 acc)
__device__ __forceinline__ void mma_bf16(float* d, const uint32_t* a,
                                         uint32_t b0, uint32_t b1) {
    asm volatile(
        "mma.sync.aligned.m16n8k16.row.col.f32.bf16.bf16.f32 "
        "{%0,%1,%2,%3}, {%4,%5,%6,%7}, {%8,%9}, {%0,%1,%2,%3};"
        : "+f"(d[0]), "+f"(d[1]), "+f"(d[2]), "+f"(d[3])
        : "r"(a[0]), "r"(a[1]), "r"(a[2]), "r"(a[3]), "r"(b0), "r"(b1));
}

__device__ __forceinline__ void cp16(void* dst_smem, const void* src) {
    uint32_t d = smem_u32(dst_smem);
    asm volatile("cp.async.cg.shared.global [%0], [%1], 16;" :: "r"(d), "l"(src) : "memory");
}
#define CP_COMMIT() asm volatile("cp.async.commit_group;" ::: "memory")

__device__ __forceinline__ void pack_hl(float v0, float v1, uint32_t& hi, uint32_t& lo) {
    __nv_bfloat162 h = __floats2bfloat162_rn(v0, v1);
    __nv_bfloat162 l = __floats2bfloat162_rn(v0 - __bfloat162float(h.x),
                                             v1 - __bfloat162float(h.y));
    hi = *(uint32_t*)&h;
    lo = *(uint32_t*)&l;
}
__device__ __forceinline__ void store_pair(__nv_bfloat16* Oh, __nv_bfloat16* Ol,
                                           size_t off, float v0, float v1) {
    __nv_bfloat162 h = __floats2bfloat162_rn(v0, v1);
    __nv_bfloat162 l = __floats2bfloat162_rn(v0 - __bfloat162float(h.x),
                                             v1 - __bfloat162float(h.y));
    *(__nv_bfloat162*)(Oh + off) = h;
    *(__nv_bfloat162*)(Ol + off) = l;
}

// =================================================================
// fused split: x (1M float4) + 4 weights (256K float4 each) -> hi/lo
// =================================================================
#define XF4 (M_TOT * D_MODEL / 4)   // 1048576
#define WF4 (WN / 4)                // 262144

__global__ __launch_bounds__(256)
void split_all(const float* __restrict__ x, const float* __restrict__ wq,
               const float* __restrict__ wk, const float* __restrict__ wv,
               const float* __restrict__ wo,
               __nv_bfloat16* __restrict__ xh, __nv_bfloat16* __restrict__ xl,
               __nv_bfloat16* __restrict__ wh, __nv_bfloat16* __restrict__ wl) {
    int i = blockIdx.x * 256 + threadIdx.x;
    const float* src;
    __nv_bfloat16 *hi, *lo;
    int off;
    if (i < XF4) {
        src = x; hi = xh; lo = xl; off = i;
    } else {
        int j = i - XF4;
        int w = j >> 18;            // /WF4
        off = j & (WF4 - 1);
        src = (w == 0) ? wq : (w == 1) ? wk : (w == 2) ? wv : wo;
        hi = wh + (size_t)w * WN;
        lo = wl + (size_t)w * WN;
    }
    float4 v = ((const float4*)src)[off];
    uint32_t h0, l0, h1, l1;
    pack_hl(v.x, v.y, h0, l0);
    pack_hl(v.z, v.w, h1, l1);
    ((uint2*)hi)[off] = make_uint2(h0, h1);
    ((uint2*)lo)[off] = make_uint2(l0, l1);
}

// =================================================================
// GEMM body: C tile [bm:bm+128, bn:bn+128] of A[.,1024] @ W[.,1024]^T
// bf16x3 compensated, cp.async 2-stage. Shared by QKV-fused + O-proj.
// MODE 0: fp32 row-major C (ldc)
// MODE 1: bf16 hi/lo -> [b,h,s,d] head layout
// MODE 3: bf16 hi/lo row-major (ldc)
// =================================================================
#define SROW 40                        // smem row stride in halves
#define STAGE_B (128 * SROW * 2)       // 10240 B per tile
#define GSTAGE (4 * STAGE_B)           // 40960 B per stage
#define GEMM_SMEM (2 * GSTAGE)         // 81920 B

__device__ __forceinline__ void gemm_body(
    char* gsm,
    const __nv_bfloat16* __restrict__ Ahi, const __nv_bfloat16* __restrict__ Alo,
    const __nv_bfloat16* __restrict__ Whi, const __nv_bfloat16* __restrict__ Wlo,
    float* __restrict__ C, __nv_bfloat16* __restrict__ Oh,
    __nv_bfloat16* __restrict__ Ol, int ldc, int MODE, int bm, int bn) {
    const int tid = threadIdx.x;
    const int wid = tid >> 5, lane = tid & 31;
    const int wm = wid >> 2, wn = wid & 3;

    float acc[4][4][4];
#pragma unroll
    for (int i = 0; i < 4; i++)
#pragma unroll
        for (int j = 0; j < 4; j++)
#pragma unroll
            for (int r = 0; r < 4; r++) acc[i][j][r] = 0.f;

    const int lrow = lane & 15, lcol = (lane >> 4) * 8;

    auto fill = [&](int st, int k0) {
        char* base = gsm + st * GSTAGE;
#pragma unroll
        for (int i = 0; i < 2; i++) {
            int c = tid + i * 256;
            int row = c >> 2, kc = (c & 3) * 8;
            int so = (row * SROW + kc) * 2;
            size_t ga = (size_t)(bm + row) * 1024 + k0 + kc;
            size_t gb = (size_t)(bn + row) * 1024 + k0 + kc;
            cp16(base + so, Ahi + ga);
            cp16(base + STAGE_B + so, Alo + ga);
            cp16(base + 2 * STAGE_B + so, Whi + gb);
            cp16(base + 3 * STAGE_B + so, Wlo + gb);
        }
        CP_COMMIT();
    };

    fill(0, 0);
    for (int ch = 0; ch < 32; ch++) {
        if (ch + 1 < 32) {
            fill((ch + 1) & 1, (ch + 1) * 32);
            asm volatile("cp.async.wait_group 1;" ::: "memory");
        } else {
            asm volatile("cp.async.wait_group 0;" ::: "memory");
        }
        __syncthreads();
        char* base = gsm + (ch & 1) * GSTAGE;
        __nv_bfloat16* sAh = (__nv_bfloat16*)base;
        __nv_bfloat16* sAl = (__nv_bfloat16*)(base + STAGE_B);
        __nv_bfloat16* sBh = (__nv_bfloat16*)(base + 2 * STAGE_B);
        __nv_bfloat16* sBl = (__nv_bfloat16*)(base + 3 * STAGE_B);

#pragma unroll
        for (int ks = 0; ks < 32; ks += 16) {
            uint32_t ah[4][4], al[4][4], bh[2][4], bl[2][4];
#pragma unroll
            for (int mi = 0; mi < 4; mi++) {
                int off = (wm * 64 + mi * 16 + lrow) * SROW + ks + lcol;
                ldsm_x4(ah[mi], smem_u32(sAh + off));
                ldsm_x4(al[mi], smem_u32(sAl + off));
            }
#pragma unroll
            for (int p = 0; p < 2; p++) {
                int off = (wn * 32 + p * 16 + lrow) * SROW + ks + lcol;
                ldsm_x4(bh[p], smem_u32(sBh + off));
                ldsm_x4(bl[p], smem_u32(sBl + off));
            }
#pragma unroll
            for (int mi = 0; mi < 4; mi++)
#pragma unroll
                for (int ni = 0; ni < 4; ni++) {
                    int p = ni >> 1, q = ni & 1;
                    mma_bf16(acc[mi][ni], ah[mi], bh[p][q], bh[p][q + 2]);
                    mma_bf16(acc[mi][ni], ah[mi], bl[p][q], bl[p][q + 2]);
                    mma_bf16(acc[mi][ni], al[mi], bh[p][q], bh[p][q + 2]);
                }
        }
        __syncthreads();
    }

    // ---- epilogue ----
    const int r_in = lane >> 2, c_in = (lane & 3) * 2;
#pragma unroll
    for (int mi = 0; mi < 4; mi++) {
#pragma unroll
        for (int ni = 0; ni < 4; ni++) {
            int m0 = bm + wm * 64 + mi * 16 + r_in;
            int n  = bn + wn * 32 + ni * 8 + c_in;
            float v0 = acc[mi][ni][0], v1 = acc[mi][ni][1];
            float v2 = acc[mi][ni][2], v3 = acc[mi][ni][3];
            if (MODE == 0) {
                *(float2*)(C + (size_t)m0 * ldc + n) = make_float2(v0, v1);
                *(float2*)(C + (size_t)(m0 + 8) * ldc + n) = make_float2(v2, v3);
            } else if (MODE == 3) {
                store_pair(Oh, Ol, (size_t)m0 * ldc + n, v0, v1);
                store_pair(Oh, Ol, (size_t)(m0 + 8) * ldc + n, v2, v3);
            } else {  // MODE 1: [b,h,s,d]
                int h = n >> 6, d = n & 63;
#pragma unroll
                for (int rr = 0; rr < 2; rr++) {
                    int m = m0 + rr * 8;
                    int b = m >> 11, s = m & 2047;
                    size_t off = ((size_t)((b * N_HEADS + h) * SEQ + s)) * HEAD_DIM + d;
                    store_pair(Oh, Ol, off, acc[mi][ni][2 * rr], acc[mi][ni][2 * rr + 1]);
                }
            }
        }
    }
}

// fused Q/K/V projections: z=0 -> Q, z=1 -> K, z=2 -> V-transposed
__global__ __launch_bounds__(256, 1)
void qkv_gemm(const __nv_bfloat16* __restrict__ xh, const __nv_bfloat16* __restrict__ xl,
              const __nv_bfloat16* __restrict__ wh, const __nv_bfloat16* __restrict__ wl,
              __nv_bfloat16* __restrict__ qh, __nv_bfloat16* __restrict__ ql,
              __nv_bfloat16* __restrict__ kh, __nv_bfloat16* __restrict__ kl,
              __nv_bfloat16* __restrict__ vth, __nv_bfloat16* __restrict__ vtl) {
    extern __shared__ char gsm[];
    const int z = blockIdx.z;
    if (z == 0) {
        gemm_body(gsm, xh, xl, wh, wl, nullptr, qh, ql, 0, 1,
                  blockIdx.y * 128, blockIdx.x * 128);
    } else if (z == 1) {
        gemm_body(gsm, xh, xl, wh + WN, wl + WN, nullptr, kh, kl, 0, 1,
                  blockIdx.y * 128, blockIdx.x * 128);
    } else {
        // V transposed: C' = wv @ x^T -> [channel][token]
        gemm_body(gsm, wh + 2 * (size_t)WN, wl + 2 * (size_t)WN, xh, xl,
                  nullptr, vth, vtl, M_TOT, 3,
                  blockIdx.x * 128, blockIdx.y * 128);
    }
}

// output projection: fp32 row-major
__global__ __launch_bounds__(256, 1)
void o_gemm(const __nv_bfloat16* __restrict__ ah, const __nv_bfloat16* __restrict__ al,
            const __nv_bfloat16* __restrict__ wh, const __nv_bfloat16* __restrict__ wl,
            float* __restrict__ out) {
    extern __shared__ char gsm[];
    gemm_body(gsm, ah, al, wh, wl, out, nullptr, nullptr, D_MODEL, 0,
              blockIdx.y * 128, blockIdx.x * 128);
}

// =================================================================
// Flash attention on mma.sync, bf16x3 compensated, causal.
// CTA: 128 q rows x full head. 8 warps, warp = 16 q rows. Key tiles 64.
// cp.async 2-stage double-buffered K/V hi/lo tiles.
// =================================================================
#define ASROW 72
#define ABUF_B (64 * ASROW * 2)        // 9216 B per tile buffer
#define ASTAGE (4 * ABUF_B)            // 36864 B per stage
#define ATTN_SMEM (2 * ASTAGE)         // 73728 B

__global__ __launch_bounds__(256, 1)
void attn_kernel(const __nv_bfloat16* __restrict__ Qh, const __nv_bfloat16* __restrict__ Ql,
                 const __nv_bfloat16* __restrict__ Kh, const __nv_bfloat16* __restrict__ Kl,
                 const __nv_bfloat16* __restrict__ Vh, const __nv_bfloat16* __restrict__ Vl,
                 __nv_bfloat16* __restrict__ Ohg, __nv_bfloat16* __restrict__ Olg) {
    extern __shared__ char asm_raw[];
    auto buf = [&](int st, int w) -> __nv_bfloat16* {
        return (__nv_bfloat16*)(asm_raw + st * ASTAGE + w * ABUF_B);
    };

    const int tid = threadIdx.x, wid = tid >> 5, lane = tid & 31;
    const int qt = blockIdx.x, bh = blockIdx.y;
    const int b = bh >> 4, h = bh & 15;
    const int q0 = qt * 128;
    const size_t qkbase = (size_t)bh * SEQ * HEAD_DIM;
    const size_t vbase = (size_t)(h * 64) * 4096 + (size_t)b * 2048;

    const int lrow = lane & 15, lcol = (lane >> 4) * 8;
    const int rA = lane >> 2;
    const int tig2 = (lane & 3) * 2;

    // ---- stage Q into fragments (scratch = stage-0 K buffers) ----
    uint32_t qfh[4][4], qfl[4][4];
    for (int ph = 0; ph < 2; ph++) {
        const __nv_bfloat16* src = ph ? Ql : Qh;
#pragma unroll
        for (int i = 0; i < 4; i++) {
            int c = tid + i * 256;
            int row = c >> 3, cc = (c & 7) * 8;
            __nv_bfloat16* dst = buf(0, row < 64 ? 0 : 1) + (row & 63) * ASROW + cc;
            *(uint4*)dst = *(const uint4*)(src + qkbase + (size_t)(q0 + row) * 64 + cc);
        }
        __syncthreads();
        int qr = wid * 16 + lrow;
        const __nv_bfloat16* bq = buf(0, qr < 64 ? 0 : 1);
        int qrl = qr & 63;
#pragma unroll
        for (int ks = 0; ks < 4; ks++) {
            if (ph == 0) ldsm_x4(qfh[ks], smem_u32(bq + qrl * ASROW + ks * 16 + lcol));
            else         ldsm_x4(qfl[ks], smem_u32(bq + qrl * ASROW + ks * 16 + lcol));
        }
        __syncthreads();
    }

    auto fillKV = [&](int st, int k0) {
#pragma unroll
        for (int i = 0; i < 2; i++) {
            int c = tid + i * 256;
            int row = c >> 3, cc = (c & 7) * 8;
            int so = row * ASROW + cc;
            cp16(buf(st, 0) + so, Kh + qkbase + (size_t)(k0 + row) * 64 + cc);
            cp16(buf(st, 1) + so, Kl + qkbase + (size_t)(k0 + row) * 64 + cc);
            cp16(buf(st, 2) + so, Vh + vbase + (size_t)row * 4096 + k0 + cc);
            cp16(buf(st, 3) + so, Vl + vbase + (size_t)row * 4096 + k0 + cc);
        }
        CP_COMMIT();
    };

    float oacc[8][4];
#pragma unroll
    for (int i = 0; i < 8; i++)
#pragma unroll
        for (int j = 0; j < 4; j++) oacc[i][j] = 0.f;
    float mMA = -1e30f, mMB = -1e30f, lA = 0.f, lB = 0.f;

    const int nt = 2 * qt + 2;
    fillKV(0, 0);
    for (int jt = 0; jt < nt; jt++) {
        const int k0 = jt * 64;
        if (jt + 1 < nt) {
            fillKV((jt + 1) & 1, (jt + 1) * 64);
            asm volatile("cp.async.wait_group 1;" ::: "memory");
        } else {
            asm volatile("cp.async.wait_group 0;" ::: "memory");
        }
        __syncthreads();
        const int st = jt & 1;
        __nv_bfloat16* sKh = buf(st, 0);
        __nv_bfloat16* sKl = buf(st, 1);
        __nv_bfloat16* sVh = buf(st, 2);
        __nv_bfloat16* sVl = buf(st, 3);

        const int wrow0 = q0 + wid * 16;
        if (k0 <= wrow0 + 15) {
            // ---- scores S = Q K^T (3 compensated combos) ----
            float sacc[8][4];
#pragma unroll
            for (int i = 0; i < 8; i++)
#pragma unroll
                for (int j = 0; j < 4; j++) sacc[i][j] = 0.f;
#pragma unroll
            for (int ks = 0; ks < 4; ks++) {
                uint32_t kfh[4][4], kfl[4][4];
#pragma unroll
                for (int p = 0; p < 4; p++) {
                    int off = (p * 16 + lrow) * ASROW + ks * 16 + lcol;
                    ldsm_x4(kfh[p], smem_u32(sKh + off));
                    ldsm_x4(kfl[p], smem_u32(sKl + off));
                }
#pragma unroll
                for (int ni = 0; ni < 8; ni++) {
                    int p = ni >> 1, qq = ni & 1;
                    mma_bf16(sacc[ni], qfh[ks], kfh[p][qq], kfh[p][qq + 2]);
                    mma_bf16(sacc[ni], qfh[ks], kfl[p][qq], kfl[p][qq + 2]);
                    mma_bf16(sacc[ni], qfl[ks], kfh[p][qq], kfh[p][qq + 2]);
                }
            }
            // ---- scale + causal mask ----
            const bool band = (k0 + 63 > wrow0);
            const int rowAg = wrow0 + rA, rowBg = rowAg + 8;
#pragma unroll
            for (int ni = 0; ni < 8; ni++) {
                int colb = k0 + ni * 8 + tig2;
#pragma unroll
                for (int e = 0; e < 4; e++) {
                    float s = sacc[ni][e] * 0.125f;
                    if (band) {
                        int col = colb + (e & 1);
                        int row = (e < 2) ? rowAg : rowBg;
                        if (col > row) s = -1e30f;
                    }
                    sacc[ni][e] = s;
                }
            }
            // ---- online softmax ----
            float mxA = -1e30f, mxB = -1e30f;
#pragma unroll
            for (int ni = 0; ni < 8; ni++) {
                mxA = fmaxf(mxA, fmaxf(sacc[ni][0], sacc[ni][1]));
                mxB = fmaxf(mxB, fmaxf(sacc[ni][2], sacc[ni][3]));
            }
            mxA = fmaxf(mxA, __shfl_xor_sync(0xffffffffu, mxA, 1));
            mxA = fmaxf(mxA, __shfl_xor_sync(0xffffffffu, mxA, 2));
            mxB = fmaxf(mxB, __shfl_xor_sync(0xffffffffu, mxB, 1));
            mxB = fmaxf(mxB, __shfl_xor_sync(0xffffffffu, mxB, 2));
            float mnA = fmaxf(mMA, mxA), mnB = fmaxf(mMB, mxB);
            float scA = __expf(mMA - mnA), scB = __expf(mMB - mnB);
            mMA = mnA; mMB = mnB;
            float suA = 0.f, suB = 0.f;
#pragma unroll
            for (int ni = 0; ni < 8; ni++) {
                sacc[ni][0] = __expf(sacc[ni][0] - mnA); suA += sacc[ni][0];
                sacc[ni][1] = __expf(sacc[ni][1] - mnA); suA += sacc[ni][1];
                sacc[ni][2] = __expf(sacc[ni][2] - mnB); suB += sacc[ni][2];
                sacc[ni][3] = __expf(sacc[ni][3] - mnB); suB += sacc[ni][3];
            }
            suA += __shfl_xor_sync(0xffffffffu, suA, 1);
            suA += __shfl_xor_sync(0xffffffffu, suA, 2);
            suB += __shfl_xor_sync(0xffffffffu, suB, 1);
            suB += __shfl_xor_sync(0xffffffffu, suB, 2);
            lA = lA * scA + suA;
            lB = lB * scB + suB;
#pragma unroll
            for (int ni = 0; ni < 8; ni++) {
                oacc[ni][0] *= scA; oacc[ni][1] *= scA;
                oacc[ni][2] *= scB; oacc[ni][3] *= scB;
            }
            // ---- O += P * V^T  (P repacked C-frag -> A-frag, hi/lo) ----
#pragma unroll
            for (int j = 0; j < 4; j++) {
                uint32_t Ph[4], Pl[4];
                pack_hl(sacc[2 * j][0],     sacc[2 * j][1],     Ph[0], Pl[0]);
                pack_hl(sacc[2 * j][2],     sacc[2 * j][3],     Ph[1], Pl[1]);
                pack_hl(sacc[2 * j + 1][0], sacc[2 * j + 1][1], Ph[2], Pl[2]);
                pack_hl(sacc[2 * j + 1][2], sacc[2 * j + 1][3], Ph[3], Pl[3]);
                uint32_t vfh[4][4], vfl[4][4];
#pragma unroll
                for (int p = 0; p < 4; p++) {
                    int off = (p * 16 + lrow) * ASROW + j * 16 + lcol;
                    ldsm_x4(vfh[p], smem_u32(sVh + off));
                    ldsm_x4(vfl[p], smem_u32(sVl + off));
                }
#pragma unroll
                for (int ni = 0; ni < 8; ni++) {
                    int p = ni >> 1, qq = ni & 1;
                    mma_bf16(oacc[ni], Ph, vfh[p][qq], vfh[p][qq + 2]);
                    mma_bf16(oacc[ni], Ph, vfl[p][qq], vfl[p][qq + 2]);
                    mma_bf16(oacc[ni], Pl, vfh[p][qq], vfh[p][qq + 2]);
                }
            }
        }
        __syncthreads();   // all warps done with stage st before it is refilled
    }

    // ---- normalize + store bf16 hi/lo to [m][1024] ----
    float iA = 1.f / lA, iB = 1.f / lB;
    int sA = q0 + wid * 16 + rA;
    size_t rowA_off = ((size_t)b * SEQ + sA) * D_MODEL + h * 64;
    size_t rowB_off = rowA_off + (size_t)8 * D_MODEL;
#pragma unroll
    for (int ni = 0; ni < 8; ni++) {
        int n = ni * 8 + tig2;
        store_pair(Ohg, Olg, rowA_off + n, oacc[ni][0] * iA, oacc[ni][1] * iA);
        store_pair(Ohg, Olg, rowB_off + n, oacc[ni][2] * iB, oacc[ni][3] * iB);
    }
}

// =================================================================
// launch
// =================================================================
extern "C" void kernel_launch(void* const* d_in, const int* in_sizes, int n_in,
                              void* d_out, int out_size) {
    const float* x  = (const float*)d_in[0];
    const float* wq = (const float*)d_in[1];
    const float* wk = (const float*)d_in[2];
    const float* wv = (const float*)d_in[3];
    const float* wo = (const float*)d_in[4];
    float* out = (float*)d_out;

    __nv_bfloat16 *xh, *xl, *wh, *wl, *qh, *ql, *kh, *kl, *vth, *vtl, *ah, *al;
    cudaGetSymbolAddress((void**)&xh, g_x_hi);
    cudaGetSymbolAddress((void**)&xl, g_x_lo);
    cudaGetSymbolAddress((void**)&wh, g_w_hi);
    cudaGetSymbolAddress((void**)&wl, g_w_lo);
    cudaGetSymbolAddress((void**)&qh, g_qh);
    cudaGetSymbolAddress((void**)&ql, g_ql);
    cudaGetSymbolAddress((void**)&kh, g_kh);
    cudaGetSymbolAddress((void**)&kl, g_kl);
    cudaGetSymbolAddress((void**)&vth, g_vth);
    cudaGetSymbolAddress((void**)&vtl, g_vtl);
    cudaGetSymbolAddress((void**)&ah, g_ah);
    cudaGetSymbolAddress((void**)&al, g_al);

    cudaFuncSetAttribute(qkv_gemm,
                         cudaFuncAttributeMaxDynamicSharedMemorySize, GEMM_SMEM);
    cudaFuncSetAttribute(o_gemm,
                         cudaFuncAttributeMaxDynamicSharedMemorySize, GEMM_SMEM);
    cudaFuncSetAttribute(attn_kernel,
                         cudaFuncAttributeMaxDynamicSharedMemorySize, ATTN_SMEM);

    // one fused split for x + all 4 weights
    split_all<<<(XF4 + 4 * WF4 + 255) / 256, 256>>>(x, wq, wk, wv, wo, xh, xl, wh, wl);

    // fused Q/K/V projections (z = 0,1,2)
    dim3 g_qkv(8, 32, 3);
    qkv_gemm<<<g_qkv, 256, GEMM_SMEM>>>(xh, xl, wh, wl, qh, ql, kh, kl, vth, vtl);

    // attention -> bf16 hi/lo [m][1024]
    dim3 g_at(SEQ / 128, BATCH * N_HEADS);    // (16, 32)
    attn_kernel<<<g_at, 256, ATTN_SMEM>>>(qh, ql, kh, kl, vth, vtl, ah, al);

    // output projection -> fp32 out
    dim3 g_o(8, 32);
    o_gemm<<<g_o, 256, GEMM_SMEM>>>(ah, al, wh + 3 * (size_t)WN, wl + 3 * (size_t)WN, out);
}

// round 9
// speedup vs baseline: 2.8158x; 1.0221x over previous
#include <cuda_runtime.h>
#include <cuda_bf16.h>
#include <cstdint>
#include <math.h>

#define D_MODEL 1024
#define N_HEADS 16
#define HEAD_DIM 64
#define BATCH 2
#define SEQ 2048
#define M_TOT (BATCH * SEQ)   // 4096
#define WN (D_MODEL * D_MODEL)

// ---------------- scratch (no allocations allowed) ----------------
__device__ __nv_bfloat16 g_x_hi[M_TOT * D_MODEL];
__device__ __nv_bfloat16 g_x_lo[M_TOT * D_MODEL];
__device__ __nv_bfloat16 g_w_hi[4 * WN];   // wq,wk,wv,wo
__device__ __nv_bfloat16 g_w_lo[4 * WN];
__device__ __nv_bfloat16 g_qh[M_TOT * D_MODEL], g_ql[M_TOT * D_MODEL];   // [b,h,s,d]
__device__ __nv_bfloat16 g_kh[M_TOT * D_MODEL], g_kl[M_TOT * D_MODEL];   // [b,h,s,d]
__device__ __nv_bfloat16 g_vth[M_TOT * D_MODEL], g_vtl[M_TOT * D_MODEL]; // [h*64+d][b*2048+s]
__device__ __nv_bfloat16 g_ah[M_TOT * D_MODEL], g_al[M_TOT * D_MODEL];   // [m][1024]

// =================== portable PTX helpers ===================
__device__ __forceinline__ uint32_t smem_u32(const void* p) {
    uint32_t a;
    asm("{ .reg .u64 t; cvta.to.shared.u64 t, %1; cvt.u32.u64 %0, t; }"
        : "=r"(a) : "l"(p));
    return a;
}

__device__ __forceinline__ void ldsm_x4(uint32_t* r, uint32_t addr) {
    asm volatile("ldmatrix.sync.aligned.m8n8.x4.shared.b16 {%0,%1,%2,%3}, [%4];"
                 : "=r"(r[0]), "=r"(r[1]), "=r"(r[2]), "=r"(r[3]) : "r"(addr));
}

// D += A * B  (m16n8k16, bf16 in, fp32 acc)
__device__ __forceinline__ void mma_bf16(float* d, const uint32_t* a,
                                         uint32_t b0, uint32_t b1) {
    asm volatile(
        "mma.sync.aligned.m16n8k16.row.col.f32.bf16.bf16.f32 "
        "{%0,%1,%2,%3}, {%4,%5,%6,%7}, {%8,%9}, {%0,%1,%2,%3};"
        : "+f"(d[0]), "+f"(d[1]), "+f"(d[2]), "+f"(d[3])
        : "r"(a[0]), "r"(a[1]), "r"(a[2]), "r"(a[3]), "r"(b0), "r"(b1));
}

__device__ __forceinline__ void cp16(void* dst_smem, const void* src) {
    uint32_t d = smem_u32(dst_smem);
    asm volatile("cp.async.cg.shared.global [%0], [%1], 16;" :: "r"(d), "l"(src) : "memory");
}
#define CP_COMMIT() asm volatile("cp.async.commit_group;" ::: "memory")

__device__ __forceinline__ void pack_hl(float v0, float v1, uint32_t& hi, uint32_t& lo) {
    __nv_bfloat162 h = __floats2bfloat162_rn(v0, v1);
    __nv_bfloat162 l = __floats2bfloat162_rn(v0 - __bfloat162float(h.x),
                                             v1 - __bfloat162float(h.y));
    hi = *(uint32_t*)&h;
    lo = *(uint32_t*)&l;
}
__device__ __forceinline__ void store_pair(__nv_bfloat16* Oh, __nv_bfloat16* Ol,
                                           size_t off, float v0, float v1) {
    __nv_bfloat162 h = __floats2bfloat162_rn(v0, v1);
    __nv_bfloat162 l = __floats2bfloat162_rn(v0 - __bfloat162float(h.x),
                                             v1 - __bfloat162float(h.y));
    *(__nv_bfloat162*)(Oh + off) = h;
    *(__nv_bfloat162*)(Ol + off) = l;
}

// =================================================================
// fused split: x (1M float4) + 4 weights (256K float4 each) -> hi/lo
// =================================================================
#define XF4 (M_TOT * D_MODEL / 4)   // 1048576
#define WF4 (WN / 4)                // 262144

__global__ __launch_bounds__(256)
void split_all(const float* __restrict__ x, const float* __restrict__ wq,
               const float* __restrict__ wk, const float* __restrict__ wv,
               const float* __restrict__ wo,
               __nv_bfloat16* __restrict__ xh, __nv_bfloat16* __restrict__ xl,
               __nv_bfloat16* __restrict__ wh, __nv_bfloat16* __restrict__ wl) {
    int i = blockIdx.x * 256 + threadIdx.x;
    const float* src;
    __nv_bfloat16 *hi, *lo;
    int off;
    if (i < XF4) {
        src = x; hi = xh; lo = xl; off = i;
    } else {
        int j = i - XF4;
        int w = j >> 18;            // /WF4
        off = j & (WF4 - 1);
        src = (w == 0) ? wq : (w == 1) ? wk : (w == 2) ? wv : wo;
        hi = wh + (size_t)w * WN;
        lo = wl + (size_t)w * WN;
    }
    float4 v = ((const float4*)src)[off];
    uint32_t h0, l0, h1, l1;
    pack_hl(v.x, v.y, h0, l0);
    pack_hl(v.z, v.w, h1, l1);
    ((uint2*)hi)[off] = make_uint2(h0, h1);
    ((uint2*)lo)[off] = make_uint2(l0, l1);
}

// =================================================================
// GEMM body: C tile [bm:bm+128, bn:bn+128] of A[.,1024] @ W[.,1024]^T
// bf16x3 compensated, cp.async 2-stage.
// MODE 0: fp32 row-major C (ldc)
// MODE 1: bf16 hi/lo -> [b,h,s,d] head layout
// MODE 3: bf16 hi/lo row-major (ldc)
// =================================================================
#define SROW 40                        // smem row stride in halves
#define STAGE_B (128 * SROW * 2)       // 10240 B per tile
#define GSTAGE (4 * STAGE_B)           // 40960 B per stage
#define GEMM_SMEM (2 * GSTAGE)         // 81920 B

__device__ __forceinline__ void gemm_body(
    char* gsm,
    const __nv_bfloat16* __restrict__ Ahi, const __nv_bfloat16* __restrict__ Alo,
    const __nv_bfloat16* __restrict__ Whi, const __nv_bfloat16* __restrict__ Wlo,
    float* __restrict__ C, __nv_bfloat16* __restrict__ Oh,
    __nv_bfloat16* __restrict__ Ol, int ldc, int MODE, int bm, int bn) {
    const int tid = threadIdx.x;
    const int wid = tid >> 5, lane = tid & 31;
    const int wm = wid >> 2, wn = wid & 3;

    float acc[4][4][4];
#pragma unroll
    for (int i = 0; i < 4; i++)
#pragma unroll
        for (int j = 0; j < 4; j++)
#pragma unroll
            for (int r = 0; r < 4; r++) acc[i][j][r] = 0.f;

    const int lrow = lane & 15, lcol = (lane >> 4) * 8;

    auto fill = [&](int st, int k0) {
        char* base = gsm + st * GSTAGE;
#pragma unroll
        for (int i = 0; i < 2; i++) {
            int c = tid + i * 256;
            int row = c >> 2, kc = (c & 3) * 8;
            int so = (row * SROW + kc) * 2;
            size_t ga = (size_t)(bm + row) * 1024 + k0 + kc;
            size_t gb = (size_t)(bn + row) * 1024 + k0 + kc;
            cp16(base + so, Ahi + ga);
            cp16(base + STAGE_B + so, Alo + ga);
            cp16(base + 2 * STAGE_B + so, Whi + gb);
            cp16(base + 3 * STAGE_B + so, Wlo + gb);
        }
        CP_COMMIT();
    };

    fill(0, 0);
    for (int ch = 0; ch < 32; ch++) {
        if (ch + 1 < 32) {
            fill((ch + 1) & 1, (ch + 1) * 32);
            asm volatile("cp.async.wait_group 1;" ::: "memory");
        } else {
            asm volatile("cp.async.wait_group 0;" ::: "memory");
        }
        __syncthreads();
        char* base = gsm + (ch & 1) * GSTAGE;
        __nv_bfloat16* sAh = (__nv_bfloat16*)base;
        __nv_bfloat16* sAl = (__nv_bfloat16*)(base + STAGE_B);
        __nv_bfloat16* sBh = (__nv_bfloat16*)(base + 2 * STAGE_B);
        __nv_bfloat16* sBl = (__nv_bfloat16*)(base + 3 * STAGE_B);

#pragma unroll
        for (int ks = 0; ks < 32; ks += 16) {
            uint32_t ah[4][4], al[4][4], bh[2][4], bl[2][4];
#pragma unroll
            for (int mi = 0; mi < 4; mi++) {
                int off = (wm * 64 + mi * 16 + lrow) * SROW + ks + lcol;
                ldsm_x4(ah[mi], smem_u32(sAh + off));
                ldsm_x4(al[mi], smem_u32(sAl + off));
            }
#pragma unroll
            for (int p = 0; p < 2; p++) {
                int off = (wn * 32 + p * 16 + lrow) * SROW + ks + lcol;
                ldsm_x4(bh[p], smem_u32(sBh + off));
                ldsm_x4(bl[p], smem_u32(sBl + off));
            }
#pragma unroll
            for (int mi = 0; mi < 4; mi++)
#pragma unroll
                for (int ni = 0; ni < 4; ni++) {
                    int p = ni >> 1, q = ni & 1;
                    mma_bf16(acc[mi][ni], ah[mi], bh[p][q], bh[p][q + 2]);
                    mma_bf16(acc[mi][ni], ah[mi], bl[p][q], bl[p][q + 2]);
                    mma_bf16(acc[mi][ni], al[mi], bh[p][q], bh[p][q + 2]);
                }
        }
        __syncthreads();
    }

    // ---- epilogue ----
    const int r_in = lane >> 2, c_in = (lane & 3) * 2;
#pragma unroll
    for (int mi = 0; mi < 4; mi++) {
#pragma unroll
        for (int ni = 0; ni < 4; ni++) {
            int m0 = bm + wm * 64 + mi * 16 + r_in;
            int n  = bn + wn * 32 + ni * 8 + c_in;
            float v0 = acc[mi][ni][0], v1 = acc[mi][ni][1];
            float v2 = acc[mi][ni][2], v3 = acc[mi][ni][3];
            if (MODE == 0) {
                *(float2*)(C + (size_t)m0 * ldc + n) = make_float2(v0, v1);
                *(float2*)(C + (size_t)(m0 + 8) * ldc + n) = make_float2(v2, v3);
            } else if (MODE == 3) {
                store_pair(Oh, Ol, (size_t)m0 * ldc + n, v0, v1);
                store_pair(Oh, Ol, (size_t)(m0 + 8) * ldc + n, v2, v3);
            } else {  // MODE 1: [b,h,s,d]
                int h = n >> 6, d = n & 63;
#pragma unroll
                for (int rr = 0; rr < 2; rr++) {
                    int m = m0 + rr * 8;
                    int b = m >> 11, s = m & 2047;
                    size_t off = ((size_t)((b * N_HEADS + h) * SEQ + s)) * HEAD_DIM + d;
                    store_pair(Oh, Ol, off, acc[mi][ni][2 * rr], acc[mi][ni][2 * rr + 1]);
                }
            }
        }
    }
}

// fused Q/K/V projections: z=0 -> Q, z=1 -> K, z=2 -> V-transposed
__global__ __launch_bounds__(256, 2)
void qkv_gemm(const __nv_bfloat16* __restrict__ xh, const __nv_bfloat16* __restrict__ xl,
              const __nv_bfloat16* __restrict__ wh, const __nv_bfloat16* __restrict__ wl,
              __nv_bfloat16* __restrict__ qh, __nv_bfloat16* __restrict__ ql,
              __nv_bfloat16* __restrict__ kh, __nv_bfloat16* __restrict__ kl,
              __nv_bfloat16* __restrict__ vth, __nv_bfloat16* __restrict__ vtl) {
    extern __shared__ char gsm[];
    const int z = blockIdx.z;
    if (z == 0) {
        gemm_body(gsm, xh, xl, wh, wl, nullptr, qh, ql, 0, 1,
                  blockIdx.y * 128, blockIdx.x * 128);
    } else if (z == 1) {
        gemm_body(gsm, xh, xl, wh + WN, wl + WN, nullptr, kh, kl, 0, 1,
                  blockIdx.y * 128, blockIdx.x * 128);
    } else {
        // V transposed: C' = wv @ x^T -> [channel][token]
        gemm_body(gsm, wh + 2 * (size_t)WN, wl + 2 * (size_t)WN, xh, xl,
                  nullptr, vth, vtl, M_TOT, 3,
                  blockIdx.x * 128, blockIdx.y * 128);
    }
}

// output projection: fp32 row-major
__global__ __launch_bounds__(256, 2)
void o_gemm(const __nv_bfloat16* __restrict__ ah, const __nv_bfloat16* __restrict__ al,
            const __nv_bfloat16* __restrict__ wh, const __nv_bfloat16* __restrict__ wl,
            float* __restrict__ out) {
    extern __shared__ char gsm[];
    gemm_body(gsm, ah, al, wh, wl, out, nullptr, nullptr, D_MODEL, 0,
              blockIdx.y * 128, blockIdx.x * 128);
}

// =================================================================
// Flash attention on mma.sync, bf16x3 compensated, causal.
// CTA: 128 q rows x full head. 8 warps, warp = 16 q rows. Key tiles 64.
// cp.async 2-stage double-buffered K/V hi/lo tiles.
// Q-hi fragments live in registers; Q-lo lives in a dedicated smem
// region and is re-materialized per tile via ldmatrix (reg pressure).
// =================================================================
#define ASROW 72
#define ABUF_B (64 * ASROW * 2)        // 9216 B per tile buffer
#define ASTAGE (4 * ABUF_B)            // 36864 B per stage
#define QL_B (128 * ASROW * 2)         // 18432 B for Q-lo
#define ATTN_SMEM (2 * ASTAGE + QL_B)  // 92160 B

__global__ __launch_bounds__(256, 2)
void attn_kernel(const __nv_bfloat16* __restrict__ Qh, const __nv_bfloat16* __restrict__ Ql,
                 const __nv_bfloat16* __restrict__ Kh, const __nv_bfloat16* __restrict__ Kl,
                 const __nv_bfloat16* __restrict__ Vh, const __nv_bfloat16* __restrict__ Vl,
                 __nv_bfloat16* __restrict__ Ohg, __nv_bfloat16* __restrict__ Olg) {
    extern __shared__ char asm_raw[];
    auto buf = [&](int st, int w) -> __nv_bfloat16* {
        return (__nv_bfloat16*)(asm_raw + st * ASTAGE + w * ABUF_B);
    };
    __nv_bfloat16* sQl = (__nv_bfloat16*)(asm_raw + 2 * ASTAGE);

    const int tid = threadIdx.x, wid = tid >> 5, lane = tid & 31;
    const int qt = blockIdx.x, bh = blockIdx.y;
    const int b = bh >> 4, h = bh & 15;
    const int q0 = qt * 128;
    const size_t qkbase = (size_t)bh * SEQ * HEAD_DIM;
    const size_t vbase = (size_t)(h * 64) * 4096 + (size_t)b * 2048;

    const int lrow = lane & 15, lcol = (lane >> 4) * 8;
    const int rA = lane >> 2;
    const int tig2 = (lane & 3) * 2;
    const int qlrow = (wid * 16 + lrow) * ASROW;   // ldsm row base in sQl

    // ---- stage Q: lo -> dedicated smem; hi -> fragments via scratch ----
#pragma unroll
    for (int i = 0; i < 4; i++) {
        int c = tid + i * 256;
        int row = c >> 3, cc = (c & 7) * 8;
        *(uint4*)(sQl + row * ASROW + cc) =
            *(const uint4*)(Ql + qkbase + (size_t)(q0 + row) * 64 + cc);
        __nv_bfloat16* dst = buf(0, row < 64 ? 0 : 1) + (row & 63) * ASROW + cc;
        *(uint4*)dst = *(const uint4*)(Qh + qkbase + (size_t)(q0 + row) * 64 + cc);
    }
    __syncthreads();
    uint32_t qfh[4][4];
    {
        int qr = wid * 16 + lrow;
        const __nv_bfloat16* bq = buf(0, qr < 64 ? 0 : 1);
        int qrl = qr & 63;
#pragma unroll
        for (int ks = 0; ks < 4; ks++)
            ldsm_x4(qfh[ks], smem_u32(bq + qrl * ASROW + ks * 16 + lcol));
    }
    __syncthreads();   // scratch free before fillKV overwrites it

    auto fillKV = [&](int st, int k0) {
#pragma unroll
        for (int i = 0; i < 2; i++) {
            int c = tid + i * 256;
            int row = c >> 3, cc = (c & 7) * 8;
            int so = row * ASROW + cc;
            cp16(buf(st, 0) + so, Kh + qkbase + (size_t)(k0 + row) * 64 + cc);
            cp16(buf(st, 1) + so, Kl + qkbase + (size_t)(k0 + row) * 64 + cc);
            cp16(buf(st, 2) + so, Vh + vbase + (size_t)row * 4096 + k0 + cc);
            cp16(buf(st, 3) + so, Vl + vbase + (size_t)row * 4096 + k0 + cc);
        }
        CP_COMMIT();
    };

    float oacc[8][4];
#pragma unroll
    for (int i = 0; i < 8; i++)
#pragma unroll
        for (int j = 0; j < 4; j++) oacc[i][j] = 0.f;
    float mMA = -1e30f, mMB = -1e30f, lA = 0.f, lB = 0.f;

    const int nt = 2 * qt + 2;
    fillKV(0, 0);
    for (int jt = 0; jt < nt; jt++) {
        const int k0 = jt * 64;
        if (jt + 1 < nt) {
            fillKV((jt + 1) & 1, (jt + 1) * 64);
            asm volatile("cp.async.wait_group 1;" ::: "memory");
        } else {
            asm volatile("cp.async.wait_group 0;" ::: "memory");
        }
        __syncthreads();
        const int st = jt & 1;
        __nv_bfloat16* sKh = buf(st, 0);
        __nv_bfloat16* sKl = buf(st, 1);
        __nv_bfloat16* sVh = buf(st, 2);
        __nv_bfloat16* sVl = buf(st, 3);

        const int wrow0 = q0 + wid * 16;
        if (k0 <= wrow0 + 15) {
            // ---- scores S = Q K^T (3 compensated combos) ----
            float sacc[8][4];
#pragma unroll
            for (int i = 0; i < 8; i++)
#pragma unroll
                for (int j = 0; j < 4; j++) sacc[i][j] = 0.f;
#pragma unroll
            for (int ks = 0; ks < 4; ks++) {
                uint32_t kfh[4][4], kfl[4][4], qfl_t[4];
                ldsm_x4(qfl_t, smem_u32(sQl + qlrow + ks * 16 + lcol));
#pragma unroll
                for (int p = 0; p < 4; p++) {
                    int off = (p * 16 + lrow) * ASROW + ks * 16 + lcol;
                    ldsm_x4(kfh[p], smem_u32(sKh + off));
                    ldsm_x4(kfl[p], smem_u32(sKl + off));
                }
#pragma unroll
                for (int ni = 0; ni < 8; ni++) {
                    int p = ni >> 1, qq = ni & 1;
                    mma_bf16(sacc[ni], qfh[ks], kfh[p][qq], kfh[p][qq + 2]);
                    mma_bf16(sacc[ni], qfh[ks], kfl[p][qq], kfl[p][qq + 2]);
                    mma_bf16(sacc[ni], qfl_t, kfh[p][qq], kfh[p][qq + 2]);
                }
            }
            // ---- scale + causal mask ----
            const bool band = (k0 + 63 > wrow0);
            const int rowAg = wrow0 + rA, rowBg = rowAg + 8;
#pragma unroll
            for (int ni = 0; ni < 8; ni++) {
                int colb = k0 + ni * 8 + tig2;
#pragma unroll
                for (int e = 0; e < 4; e++) {
                    float s = sacc[ni][e] * 0.125f;
                    if (band) {
                        int col = colb + (e & 1);
                        int row = (e < 2) ? rowAg : rowBg;
                        if (col > row) s = -1e30f;
                    }
                    sacc[ni][e] = s;
                }
            }
            // ---- online softmax ----
            float mxA = -1e30f, mxB = -1e30f;
#pragma unroll
            for (int ni = 0; ni < 8; ni++) {
                mxA = fmaxf(mxA, fmaxf(sacc[ni][0], sacc[ni][1]));
                mxB = fmaxf(mxB, fmaxf(sacc[ni][2], sacc[ni][3]));
            }
            mxA = fmaxf(mxA, __shfl_xor_sync(0xffffffffu, mxA, 1));
            mxA = fmaxf(mxA, __shfl_xor_sync(0xffffffffu, mxA, 2));
            mxB = fmaxf(mxB, __shfl_xor_sync(0xffffffffu, mxB, 1));
            mxB = fmaxf(mxB, __shfl_xor_sync(0xffffffffu, mxB, 2));
            float mnA = fmaxf(mMA, mxA), mnB = fmaxf(mMB, mxB);
            float scA = __expf(mMA - mnA), scB = __expf(mMB - mnB);
            mMA = mnA; mMB = mnB;
            float suA = 0.f, suB = 0.f;
#pragma unroll
            for (int ni = 0; ni < 8; ni++) {
                sacc[ni][0] = __expf(sacc[ni][0] - mnA); suA += sacc[ni][0];
                sacc[ni][1] = __expf(sacc[ni][1] - mnA); suA += sacc[ni][1];
                sacc[ni][2] = __expf(sacc[ni][2] - mnB); suB += sacc[ni][2];
                sacc[ni][3] = __expf(sacc[ni][3] - mnB); suB += sacc[ni][3];
            }
            suA += __shfl_xor_sync(0xffffffffu, suA, 1);
            suA += __shfl_xor_sync(0xffffffffu, suA, 2);
            suB += __shfl_xor_sync(0xffffffffu, suB, 1);
            suB += __shfl_xor_sync(0xffffffffu, suB, 2);
            lA = lA * scA + suA;
            lB = lB * scB + suB;
#pragma unroll
            for (int ni = 0; ni < 8; ni++) {
                oacc[ni][0] *= scA; oacc[ni][1] *= scA;
                oacc[ni][2] *= scB; oacc[ni][3] *= scB;
            }
            // ---- O += P * V^T  (P repacked C-frag -> A-frag, hi/lo) ----
#pragma unroll
            for (int j = 0; j < 4; j++) {
                uint32_t Ph[4], Pl[4];
                pack_hl(sacc[2 * j][0],     sacc[2 * j][1],     Ph[0], Pl[0]);
                pack_hl(sacc[2 * j][2],     sacc[2 * j][3],     Ph[1], Pl[1]);
                pack_hl(sacc[2 * j + 1][0], sacc[2 * j + 1][1], Ph[2], Pl[2]);
                pack_hl(sacc[2 * j + 1][2], sacc[2 * j + 1][3], Ph[3], Pl[3]);
                uint32_t vfh[4][4], vfl[4][4];
#pragma unroll
                for (int p = 0; p < 4; p++) {
                    int off = (p * 16 + lrow) * ASROW + j * 16 + lcol;
                    ldsm_x4(vfh[p], smem_u32(sVh + off));
                    ldsm_x4(vfl[p], smem_u32(sVl + off));
                }
#pragma unroll
                for (int ni = 0; ni < 8; ni++) {
                    int p = ni >> 1, qq = ni & 1;
                    mma_bf16(oacc[ni], Ph, vfh[p][qq], vfh[p][qq + 2]);
                    mma_bf16(oacc[ni], Ph, vfl[p][qq], vfl[p][qq + 2]);
                    mma_bf16(oacc[ni], Pl, vfh[p][qq], vfh[p][qq + 2]);
                }
            }
        }
        __syncthreads();   // all warps done with stage st before it is refilled
    }

    // ---- normalize + store bf16 hi/lo to [m][1024] ----
    float iA = 1.f / lA, iB = 1.f / lB;
    int sA = q0 + wid * 16 + rA;
    size_t rowA_off = ((size_t)b * SEQ + sA) * D_MODEL + h * 64;
    size_t rowB_off = rowA_off + (size_t)8 * D_MODEL;
#pragma unroll
    for (int ni = 0; ni < 8; ni++) {
        int n = ni * 8 + tig2;
        store_pair(Ohg, Olg, rowA_off + n, oacc[ni][0] * iA, oacc[ni][1] * iA);
        store_pair(Ohg, Olg, rowB_off + n, oacc[ni][2] * iB, oacc[ni][3] * iB);
    }
}

// =================================================================
// launch
// =================================================================
extern "C" void kernel_launch(void* const* d_in, const int* in_sizes, int n_in,
                              void* d_out, int out_size) {
    const float* x  = (const float*)d_in[0];
    const float* wq = (const float*)d_in[1];
    const float* wk = (const float*)d_in[2];
    const float* wv = (const float*)d_in[3];
    const float* wo = (const float*)d_in[4];
    float* out = (float*)d_out;

    __nv_bfloat16 *xh, *xl, *wh, *wl, *qh, *ql, *kh, *kl, *vth, *vtl, *ah, *al;
    cudaGetSymbolAddress((void**)&xh, g_x_hi);
    cudaGetSymbolAddress((void**)&xl, g_x_lo);
    cudaGetSymbolAddress((void**)&wh, g_w_hi);
    cudaGetSymbolAddress((void**)&wl, g_w_lo);
    cudaGetSymbolAddress((void**)&qh, g_qh);
    cudaGetSymbolAddress((void**)&ql, g_ql);
    cudaGetSymbolAddress((void**)&kh, g_kh);
    cudaGetSymbolAddress((void**)&kl, g_kl);
    cudaGetSymbolAddress((void**)&vth, g_vth);
    cudaGetSymbolAddress((void**)&vtl, g_vtl);
    cudaGetSymbolAddress((void**)&ah, g_ah);
    cudaGetSymbolAddress((void**)&al, g_al);

    cudaFuncSetAttribute(qkv_gemm,
                         cudaFuncAttributeMaxDynamicSharedMemorySize, GEMM_SMEM);
    cudaFuncSetAttribute(o_gemm,
                         cudaFuncAttributeMaxDynamicSharedMemorySize, GEMM_SMEM);
    cudaFuncSetAttribute(attn_kernel,
                         cudaFuncAttributeMaxDynamicSharedMemorySize, ATTN_SMEM);

    // one fused split for x + all 4 weights
    split_all<<<(XF4 + 4 * WF4 + 255) / 256, 256>>>(x, wq, wk, wv, wo, xh, xl, wh, wl);

    // fused Q/K/V projections (z = 0,1,2)
    dim3 g_qkv(8, 32, 3);
    qkv_gemm<<<g_qkv, 256, GEMM_SMEM>>>(xh, xl, wh, wl, qh, ql, kh, kl, vth, vtl);

    // attention -> bf16 hi/lo [m][1024]
    dim3 g_at(SEQ / 128, BATCH * N_HEADS);    // (16, 32)
    attn_kernel<<<g_at, 256, ATTN_SMEM>>>(qh, ql, kh, kl, vth, vtl, ah, al);

    // output projection -> fp32 out
    dim3 g_o(8, 32);
    o_gemm<<<g_o, 256, GEMM_SMEM>>>(ah, al, wh + 3 * (size_t)WN, wl + 3 * (size_t)WN, out);
}